// round 3
// baseline (speedup 1.0000x reference)
#include <cuda_runtime.h>
#include <math.h>

// Problem constants
#define HH      512
#define BQ      128
#define MIDN    2048
#define NANS    3129
#define NNODES  131072
#define NEDGES  262144

// ---------------- scratch (static __device__, no allocation) ----------------
__device__ float g_poolIN[BQ * HH];          // img node pool
__device__ float g_poolKN[BQ * HH];          // kg  node pool
__device__ float g_poolIE[BQ * HH];          // img edge pool (also used as kg edge pool per source bug)
__device__ float g_qpart[4 * BQ * 1024];     // split-K partials for [q_edge | q_node]
__device__ float g_h0[BQ * 1024];            // assembled input to W1
__device__ float g_h1part[2 * BQ * MIDN];    // split-K partials for W1
__device__ float g_h[BQ * MIDN];             // elu output
__device__ float g_outpart[3 * BQ * NANS];   // split-K partials for W2

// ---------------- segment mean (sorted segments -> contiguous ranges) -------
__global__ __launch_bounds__(256) void seg_mean(const float* __restrict__ feat,
                                                const int* __restrict__ seg,
                                                int n, float* __restrict__ out) {
    int b = blockIdx.y;
    int c = blockIdx.x * 256 + threadIdx.x;   // column in [0,512)

    // lower_bound(seg, b) and lower_bound(seg, b+1) — warp-uniform, broadcast loads
    int lo = 0, hi = n;
    while (lo < hi) { int mid = (lo + hi) >> 1; if (seg[mid] < b) lo = mid + 1; else hi = mid; }
    int s0 = lo;
    hi = n;
    while (lo < hi) { int mid = (lo + hi) >> 1; if (seg[mid] < b + 1) lo = mid + 1; else hi = mid; }
    int s1 = lo;

    float a0=0.f,a1=0.f,a2=0.f,a3=0.f,a4=0.f,a5=0.f,a6=0.f,a7=0.f;
    const float* p = feat + (size_t)s0 * HH + c;
    int r = s0;
    for (; r + 8 <= s1; r += 8) {
        a0 += p[0*HH]; a1 += p[1*HH]; a2 += p[2*HH]; a3 += p[3*HH];
        a4 += p[4*HH]; a5 += p[5*HH]; a6 += p[6*HH]; a7 += p[7*HH];
        p += 8 * HH;
    }
    float acc = 0.f;
    for (; r < s1; ++r) { acc += *p; p += HH; }
    acc += (a0+a1)+(a2+a3)+((a4+a5)+(a6+a7));
    int cnt = s1 - s0; if (cnt < 1) cnt = 1;
    out[b * HH + c] = acc / (float)cnt;
}

// ---------------- fp32 tiled GEMM with deterministic split-K ----------------
// C_part[z] = A[M,K-slice] * B[K-slice,N]   (row-major). BM=BN=64, BK=16,
// 256 threads, 4x4 register tile per thread. M must be a multiple of 64.
__global__ __launch_bounds__(256) void gemm_splitk(const float* __restrict__ A,
                                                   const float* __restrict__ B,
                                                   float* __restrict__ Cpart,
                                                   int M, int N, int K,
                                                   int ldc, int col0) {
    __shared__ float As[16][68];   // padded, stores A tile transposed [k][m]
    __shared__ float Bs[16][64];

    const int z = blockIdx.z, Z = gridDim.z;
    const int ksteps = K >> 4;
    const int kt0 = (int)(((long long)ksteps * z) / Z);
    const int kt1 = (int)(((long long)ksteps * (z + 1)) / Z);

    const int m0 = blockIdx.y * 64;
    const int n0 = blockIdx.x * 64;
    const int tid = threadIdx.x;
    const int tx = tid & 15, ty = tid >> 4;

    const int arow = tid >> 2, acol = (tid & 3) << 2;   // A tile loader coords
    const int brow = tid >> 4, bcol = (tid & 15) << 2;  // B tile loader coords

    const float* Ap = A + (size_t)(m0 + arow) * K + (kt0 << 4) + acol;
    const float* Bp = B + (size_t)((kt0 << 4) + brow) * N + n0 + bcol;
    const bool bfull = (n0 + 64 <= N) && ((N & 3) == 0);

    float acc[4][4];
#pragma unroll
    for (int i = 0; i < 4; ++i)
#pragma unroll
        for (int j = 0; j < 4; ++j) acc[i][j] = 0.f;

    for (int kt = kt0; kt < kt1; ++kt) {
        float4 av = *(const float4*)Ap;
        float4 bv;
        if (bfull) {
            bv = *(const float4*)Bp;
        } else {
            int nb = n0 + bcol;
            bv.x = (nb + 0 < N) ? Bp[0] : 0.f;
            bv.y = (nb + 1 < N) ? Bp[1] : 0.f;
            bv.z = (nb + 2 < N) ? Bp[2] : 0.f;
            bv.w = (nb + 3 < N) ? Bp[3] : 0.f;
        }
        As[acol + 0][arow] = av.x;
        As[acol + 1][arow] = av.y;
        As[acol + 2][arow] = av.z;
        As[acol + 3][arow] = av.w;
        *(float4*)&Bs[brow][bcol] = bv;
        __syncthreads();
#pragma unroll
        for (int k = 0; k < 16; ++k) {
            float4 a = *(const float4*)&As[k][ty << 2];
            float4 b = *(const float4*)&Bs[k][tx << 2];
            acc[0][0] += a.x * b.x; acc[0][1] += a.x * b.y; acc[0][2] += a.x * b.z; acc[0][3] += a.x * b.w;
            acc[1][0] += a.y * b.x; acc[1][1] += a.y * b.y; acc[1][2] += a.y * b.z; acc[1][3] += a.y * b.w;
            acc[2][0] += a.z * b.x; acc[2][1] += a.z * b.y; acc[2][2] += a.z * b.z; acc[2][3] += a.z * b.w;
            acc[3][0] += a.w * b.x; acc[3][1] += a.w * b.y; acc[3][2] += a.w * b.z; acc[3][3] += a.w * b.w;
        }
        __syncthreads();
        Ap += 16;
        Bp += (size_t)16 * N;
    }

    float* Cp = Cpart + (size_t)z * M * ldc + (size_t)(m0 + (ty << 2)) * ldc + col0 + n0 + (tx << 2);
#pragma unroll
    for (int i = 0; i < 4; ++i)
#pragma unroll
        for (int j = 0; j < 4; ++j) {
            int n = n0 + (tx << 2) + j;
            if (n < N) Cp[(size_t)i * ldc + j] = acc[i][j];
        }
}

// ---------------- assemble h0 = q_img + q_kg (with pool fusion) -------------
// h0[:, :512] = 2*(q_edge + bqe + poolIE)        (kg_edges == img_edges, source bug)
// h0[:, 512:] = 2*(q_node + bqn) + poolIN + poolKN
__global__ __launch_bounds__(256) void build_h0(const float* __restrict__ bqe,
                                                const float* __restrict__ bqn) {
    int idx = blockIdx.x * 256 + threadIdx.x;   // 128*1024
    int b = idx >> 10, j = idx & 1023;
    float s = 0.f;
#pragma unroll
    for (int z = 0; z < 4; ++z) s += g_qpart[z * (BQ * 1024) + idx];
    float r;
    if (j < 512) {
        r = 2.f * (s + bqe[j] + g_poolIE[b * HH + j]);
    } else {
        int jj = j - 512;
        r = 2.f * (s + bqn[jj]) + g_poolIN[b * HH + jj] + g_poolKN[b * HH + jj];
    }
    g_h0[idx] = r;
}

// ---------------- reduce split-K + bias + elu -------------------------------
__global__ __launch_bounds__(256) void reduce_elu(const float* __restrict__ b1) {
    int idx = blockIdx.x * 256 + threadIdx.x;   // 128*2048
    float s = g_h1part[idx] + g_h1part[BQ * MIDN + idx] + b1[idx & (MIDN - 1)];
    g_h[idx] = (s > 0.f) ? s : expm1f(s);
}

// ---------------- reduce split-K + bias -> final output ---------------------
__global__ __launch_bounds__(256) void reduce_out(const float* __restrict__ b2,
                                                  float* __restrict__ out) {
    int idx = blockIdx.x * 256 + threadIdx.x;
    if (idx >= BQ * NANS) return;
    float s = g_outpart[idx] + g_outpart[BQ * NANS + idx] + g_outpart[2 * BQ * NANS + idx]
            + b2[idx % NANS];
    out[idx] = s;
}

// ---------------- launcher ---------------------------------------------------
extern "C" void kernel_launch(void* const* d_in, const int* in_sizes, int n_in,
                              void* d_out, int out_size) {
    const float* question      = (const float*)d_in[0];
    const float* img_node_feat = (const float*)d_in[1];
    const float* kg_node_feat  = (const float*)d_in[2];
    const float* img_edge_feat = (const float*)d_in[3];
    // d_in[4] (kg_edge_feat) is dead per the faithful source bug
    const int*   img_node_seg  = (const int*)d_in[5];
    const int*   kg_node_seg   = (const int*)d_in[6];
    const int*   img_edge_seg  = (const int*)d_in[7];
    // d_in[8] (kg_edge_seg) dead
    const float* Wqe = (const float*)d_in[9];
    const float* bqe = (const float*)d_in[10];
    const float* Wqn = (const float*)d_in[11];
    const float* bqn = (const float*)d_in[12];
    const float* W1  = (const float*)d_in[13];
    const float* b1  = (const float*)d_in[14];
    const float* W2  = (const float*)d_in[15];
    const float* b2  = (const float*)d_in[16];
    float* out = (float*)d_out;

    float *poolIN, *poolKN, *poolIE, *qpart, *h0, *h1part, *h, *outpart;
    cudaGetSymbolAddress((void**)&poolIN,  g_poolIN);
    cudaGetSymbolAddress((void**)&poolKN,  g_poolKN);
    cudaGetSymbolAddress((void**)&poolIE,  g_poolIE);
    cudaGetSymbolAddress((void**)&qpart,   g_qpart);
    cudaGetSymbolAddress((void**)&h0,      g_h0);
    cudaGetSymbolAddress((void**)&h1part,  g_h1part);
    cudaGetSymbolAddress((void**)&h,       g_h);
    cudaGetSymbolAddress((void**)&outpart, g_outpart);

    // 1) segment mean pools (HBM-bound bulk of the work)
    dim3 pg(2, BQ);
    seg_mean<<<pg, 256>>>(img_node_feat, img_node_seg, NNODES, poolIN);
    seg_mean<<<pg, 256>>>(kg_node_feat,  kg_node_seg,  NNODES, poolKN);
    seg_mean<<<pg, 256>>>(img_edge_feat, img_edge_seg, NEDGES, poolIE);

    // 2) q projections into shared partial buffer [q_edge | q_node], split-K=4
    gemm_splitk<<<dim3(8, 2, 4), 256>>>(question, Wqe, qpart, BQ, 512, 1024, 1024, 0);
    gemm_splitk<<<dim3(8, 2, 4), 256>>>(question, Wqn, qpart, BQ, 512, 1024, 1024, 512);

    // 3) assemble h0
    build_h0<<<(BQ * 1024) / 256, 256>>>(bqe, bqn);

    // 4) W1 GEMM (split-K=2 -> 128 blocks) + elu reduce
    gemm_splitk<<<dim3(MIDN / 64, 2, 2), 256>>>(h0, W1, h1part, BQ, MIDN, 1024, MIDN, 0);
    reduce_elu<<<(BQ * MIDN) / 256, 256>>>(b1);

    // 5) W2 GEMM (N=3129 odd: guarded scalar B loads; split-K=3 -> 294 blocks)
    gemm_splitk<<<dim3((NANS + 63) / 64, 2, 3), 256>>>(h, W2, outpart, BQ, NANS, MIDN, NANS, 0);
    reduce_out<<<(BQ * NANS + 255) / 256, 256>>>(b2, out);
}

// round 5
// speedup vs baseline: 1.6348x; 1.6348x over previous
#include <cuda_runtime.h>
#include <math.h>

#define HH      512
#define BQ      128
#define MIDN    2048
#define NANS    3129
#define NNODES  131072
#define NEDGES  262144

#define SEGS    8      // row splits per (array, batch)
#define ZQ      16     // split-K for fused q projection
#define Z1      8      // split-K for W1
#define Z2      5      // split-K for W2

// ---------------- scratch (static __device__, no allocation) ----------------
__device__ float g_poolpart[3 * SEGS * BQ * HH];   // 6 MB
__device__ int   g_cnt[3 * BQ];
__device__ float g_qpart[ZQ * BQ * 1024];          // 8 MB
__device__ float g_h0[BQ * 1024];
__device__ float g_h1part[Z1 * BQ * MIDN];         // 8 MB
__device__ float g_h[BQ * MIDN];
__device__ float g_outpart[Z2 * BQ * NANS];        // 7.6 MB

// ---------------- fused segment-sum partials (3 arrays, 8-way row split) ----
__global__ __launch_bounds__(128) void seg_part(const float* __restrict__ f0,
                                                const float* __restrict__ f1,
                                                const float* __restrict__ f2,
                                                const int* __restrict__ sg0,
                                                const int* __restrict__ sg1,
                                                const int* __restrict__ sg2) {
    int arr = blockIdx.z;
    const float* feat = (arr == 0) ? f0 : (arr == 1) ? f1 : f2;
    const int*   seg  = (arr == 0) ? sg0 : (arr == 1) ? sg1 : sg2;
    int n = (arr == 2) ? NEDGES : NNODES;
    int b = blockIdx.y, s = blockIdx.x;

    int lo = 0, hi = n;
    while (lo < hi) { int m = (lo + hi) >> 1; if (seg[m] < b) lo = m + 1; else hi = m; }
    int st0 = lo; hi = n;
    while (lo < hi) { int m = (lo + hi) >> 1; if (seg[m] < b + 1) lo = m + 1; else hi = m; }
    int cnt = lo - st0;
    int r0 = st0 + (int)((long long)cnt * s / SEGS);
    int r1 = st0 + (int)((long long)cnt * (s + 1) / SEGS);

    const float4* p = (const float4*)feat + (size_t)r0 * 128 + threadIdx.x;
    float4 a0 = {0,0,0,0}, a1 = a0, a2 = a0, a3 = a0, a4 = a0, a5 = a0, a6 = a0, a7 = a0;
    int r = r0;
    for (; r + 8 <= r1; r += 8) {
        float4 v0 = p[0*128], v1 = p[1*128], v2 = p[2*128], v3 = p[3*128];
        float4 v4 = p[4*128], v5 = p[5*128], v6 = p[6*128], v7 = p[7*128];
        a0.x+=v0.x; a0.y+=v0.y; a0.z+=v0.z; a0.w+=v0.w;
        a1.x+=v1.x; a1.y+=v1.y; a1.z+=v1.z; a1.w+=v1.w;
        a2.x+=v2.x; a2.y+=v2.y; a2.z+=v2.z; a2.w+=v2.w;
        a3.x+=v3.x; a3.y+=v3.y; a3.z+=v3.z; a3.w+=v3.w;
        a4.x+=v4.x; a4.y+=v4.y; a4.z+=v4.z; a4.w+=v4.w;
        a5.x+=v5.x; a5.y+=v5.y; a5.z+=v5.z; a5.w+=v5.w;
        a6.x+=v6.x; a6.y+=v6.y; a6.z+=v6.z; a6.w+=v6.w;
        a7.x+=v7.x; a7.y+=v7.y; a7.z+=v7.z; a7.w+=v7.w;
        p += 8 * 128;
    }
    for (; r < r1; ++r) {
        float4 v = p[0];
        a0.x+=v.x; a0.y+=v.y; a0.z+=v.z; a0.w+=v.w;
        p += 128;
    }
    float4 t;
    t.x = ((a0.x+a1.x)+(a2.x+a3.x)) + ((a4.x+a5.x)+(a6.x+a7.x));
    t.y = ((a0.y+a1.y)+(a2.y+a3.y)) + ((a4.y+a5.y)+(a6.y+a7.y));
    t.z = ((a0.z+a1.z)+(a2.z+a3.z)) + ((a4.z+a5.z)+(a6.z+a7.z));
    t.w = ((a0.w+a1.w)+(a2.w+a3.w)) + ((a4.w+a5.w)+(a6.w+a7.w));
    float4* outp = (float4*)g_poolpart + (size_t)((arr * SEGS + s) * BQ + b) * 128 + threadIdx.x;
    *outp = t;
}

// ---------------- segment counts --------------------------------------------
__global__ void count_seg(const int* __restrict__ sg0, const int* __restrict__ sg1,
                          const int* __restrict__ sg2) {
    int t = threadIdx.x;
    if (t >= 384) return;
    int arr = t >> 7, b = t & 127;
    const int* seg = (arr == 0) ? sg0 : (arr == 1) ? sg1 : sg2;
    int n = (arr == 2) ? NEDGES : NNODES;
    int lo = 0, hi = n;
    while (lo < hi) { int m = (lo + hi) >> 1; if (seg[m] < b) lo = m + 1; else hi = m; }
    int s0 = lo; hi = n;
    while (lo < hi) { int m = (lo + hi) >> 1; if (seg[m] < b + 1) lo = m + 1; else hi = m; }
    int c = lo - s0;
    g_cnt[t] = (c < 1) ? 1 : c;
}

// ---------------- 128x128x8 fp32 GEMM, 8x8 thread tile, split-K -------------
// M fixed = 128. C_part[z] = A[128, kslice] * B[kslice, N]. B selected per
// n-block from {B1,B2} (fused q projection); N1 = cols per region = ldb.
__global__ __launch_bounds__(256) void gemm128(const float* __restrict__ A,
                                               const float* __restrict__ B1,
                                               const float* __restrict__ B2,
                                               int N1, float* __restrict__ Cpart,
                                               int Ntot, int K, int ldb, int vec) {
    __shared__ float As[8][132];
    __shared__ float Bs[8][128];

    const int z = blockIdx.y, Z = gridDim.y;
    const int ktiles = K >> 3;
    const int kt0 = (int)(((long long)ktiles * z) / Z);
    const int kt1 = (int)(((long long)ktiles * (z + 1)) / Z);
    const int n0 = blockIdx.x * 128;

    const float* Bbase; int nb;
    if (n0 < N1) { Bbase = B1; nb = n0; } else { Bbase = B2; nb = n0 - N1; }

    const int tid = threadIdx.x;
    const int tx = tid & 15, ty = tid >> 4;
    const int arow = tid >> 1, acol = (tid & 1) << 2;
    const int brow = tid >> 5, bcol = (tid & 31) << 2;

    const float* Ap = A + (size_t)arow * K + (kt0 << 3) + acol;
    const float* Bp = Bbase + (size_t)((kt0 << 3) + brow) * ldb + nb + bcol;

    float acc[8][8];
#pragma unroll
    for (int i = 0; i < 8; ++i)
#pragma unroll
        for (int j = 0; j < 8; ++j) acc[i][j] = 0.f;

    // prefetch first tile
    float4 av = *(const float4*)Ap;
    float4 bv;
    if (vec) {
        bv = *(const float4*)Bp;
    } else {
        int c = nb + bcol;
        bv.x = (c + 0 < ldb) ? Bp[0] : 0.f;
        bv.y = (c + 1 < ldb) ? Bp[1] : 0.f;
        bv.z = (c + 2 < ldb) ? Bp[2] : 0.f;
        bv.w = (c + 3 < ldb) ? Bp[3] : 0.f;
    }

    for (int kt = kt0; kt < kt1; ++kt) {
        As[acol + 0][arow] = av.x;
        As[acol + 1][arow] = av.y;
        As[acol + 2][arow] = av.z;
        As[acol + 3][arow] = av.w;
        *(float4*)&Bs[brow][bcol] = bv;
        __syncthreads();

        if (kt + 1 < kt1) {           // software-pipeline next tile's loads
            Ap += 8;
            Bp += (size_t)8 * ldb;
            av = *(const float4*)Ap;
            if (vec) {
                bv = *(const float4*)Bp;
            } else {
                int c = nb + bcol;
                bv.x = (c + 0 < ldb) ? Bp[0] : 0.f;
                bv.y = (c + 1 < ldb) ? Bp[1] : 0.f;
                bv.z = (c + 2 < ldb) ? Bp[2] : 0.f;
                bv.w = (c + 3 < ldb) ? Bp[3] : 0.f;
            }
        }

#pragma unroll
        for (int k = 0; k < 8; ++k) {
            float4 a0 = *(const float4*)&As[k][ty << 2];
            float4 a1 = *(const float4*)&As[k][(ty << 2) + 64];
            float4 b0 = *(const float4*)&Bs[k][tx << 2];
            float4 b1 = *(const float4*)&Bs[k][(tx << 2) + 64];
            float ar[8] = {a0.x,a0.y,a0.z,a0.w,a1.x,a1.y,a1.z,a1.w};
            float br[8] = {b0.x,b0.y,b0.z,b0.w,b1.x,b1.y,b1.z,b1.w};
#pragma unroll
            for (int i = 0; i < 8; ++i)
#pragma unroll
                for (int j = 0; j < 8; ++j) acc[i][j] += ar[i] * br[j];
        }
        __syncthreads();
    }

    // store partials (ldc == Ntot)
#pragma unroll
    for (int ri = 0; ri < 2; ++ri)
#pragma unroll
        for (int i = 0; i < 4; ++i) {
            int m = ri * 64 + (ty << 2) + i;
            float* Cp = Cpart + ((size_t)z * 128 + m) * Ntot + n0;
#pragma unroll
            for (int rj = 0; rj < 2; ++rj)
#pragma unroll
                for (int j = 0; j < 4; ++j) {
                    int c = rj * 64 + (tx << 2) + j;
                    if (n0 + c < Ntot) Cp[c] = acc[ri * 4 + i][rj * 4 + j];
                }
        }
}

// ---------------- assemble h0 = q_img + q_kg (pool means fused) -------------
__global__ __launch_bounds__(256) void build_h0(const float* __restrict__ bqe,
                                                const float* __restrict__ bqn) {
    int idx = blockIdx.x * 256 + threadIdx.x;   // 128*1024
    int b = idx >> 10, j = idx & 1023;
    float qs = 0.f;
#pragma unroll
    for (int z = 0; z < ZQ; ++z) qs += g_qpart[(size_t)z * (BQ * 1024) + idx];
    float r;
    if (j < 512) {
        float pe = 0.f;
#pragma unroll
        for (int s = 0; s < SEGS; ++s)
            pe += g_poolpart[(size_t)((2 * SEGS + s) * BQ + b) * HH + j];
        r = 2.f * (qs + bqe[j] + pe / (float)g_cnt[2 * BQ + b]);
    } else {
        int jj = j - 512;
        float p0 = 0.f, p1 = 0.f;
#pragma unroll
        for (int s = 0; s < SEGS; ++s) {
            p0 += g_poolpart[(size_t)((0 * SEGS + s) * BQ + b) * HH + jj];
            p1 += g_poolpart[(size_t)((1 * SEGS + s) * BQ + b) * HH + jj];
        }
        r = 2.f * (qs + bqn[jj]) + p0 / (float)g_cnt[b] + p1 / (float)g_cnt[BQ + b];
    }
    g_h0[idx] = r;
}

// ---------------- reduce split-K + bias + elu -------------------------------
__global__ __launch_bounds__(256) void reduce_elu(const float* __restrict__ b1) {
    int idx = blockIdx.x * 256 + threadIdx.x;   // 128*2048
    float s = b1[idx & (MIDN - 1)];
#pragma unroll
    for (int z = 0; z < Z1; ++z) s += g_h1part[(size_t)z * (BQ * MIDN) + idx];
    g_h[idx] = (s > 0.f) ? s : expm1f(s);
}

// ---------------- reduce split-K + bias -> output ---------------------------
__global__ __launch_bounds__(256) void reduce_out(const float* __restrict__ b2,
                                                  float* __restrict__ out) {
    int idx = blockIdx.x * 256 + threadIdx.x;
    if (idx >= BQ * NANS) return;
    float s = b2[idx % NANS];
#pragma unroll
    for (int z = 0; z < Z2; ++z) s += g_outpart[(size_t)z * (BQ * NANS) + idx];
    out[idx] = s;
}

// ---------------- launcher ---------------------------------------------------
extern "C" void kernel_launch(void* const* d_in, const int* in_sizes, int n_in,
                              void* d_out, int out_size) {
    const float* question      = (const float*)d_in[0];
    const float* img_node_feat = (const float*)d_in[1];
    const float* kg_node_feat  = (const float*)d_in[2];
    const float* img_edge_feat = (const float*)d_in[3];
    // d_in[4] kg_edge_feat dead (faithful source bug)
    const int*   img_node_seg  = (const int*)d_in[5];
    const int*   kg_node_seg   = (const int*)d_in[6];
    const int*   img_edge_seg  = (const int*)d_in[7];
    // d_in[8] kg_edge_seg dead
    const float* Wqe = (const float*)d_in[9];
    const float* bqe = (const float*)d_in[10];
    const float* Wqn = (const float*)d_in[11];
    const float* bqn = (const float*)d_in[12];
    const float* W1  = (const float*)d_in[13];
    const float* b1  = (const float*)d_in[14];
    const float* W2  = (const float*)d_in[15];
    const float* b2  = (const float*)d_in[16];
    float* out = (float*)d_out;

    float *qpart, *h0, *h1part, *h, *outpart;
    cudaGetSymbolAddress((void**)&qpart,   g_qpart);
    cudaGetSymbolAddress((void**)&h0,      g_h0);
    cudaGetSymbolAddress((void**)&h1part,  g_h1part);
    cudaGetSymbolAddress((void**)&h,       g_h);
    cudaGetSymbolAddress((void**)&outpart, g_outpart);

    // 1) all 3 pools in one launch (3072 blocks) + counts
    seg_part<<<dim3(SEGS, BQ, 3), 128>>>(img_node_feat, kg_node_feat, img_edge_feat,
                                         img_node_seg, kg_node_seg, img_edge_seg);
    count_seg<<<1, 384>>>(img_node_seg, kg_node_seg, img_edge_seg);

    // 2) fused q projection: C[:, :512]=q@Wqe, C[:, 512:]=q@Wqn (128 blocks)
    gemm128<<<dim3(8, ZQ), 256>>>(question, Wqe, Wqn, 512, qpart, 1024, 1024, 512, 1);

    // 3) assemble h0
    build_h0<<<(BQ * 1024) / 256, 256>>>(bqe, bqn);

    // 4) W1 GEMM (128 blocks) + elu reduce
    gemm128<<<dim3(16, Z1), 256>>>(h0, W1, W1, 1 << 30, h1part, MIDN, 1024, MIDN, 1);
    reduce_elu<<<(BQ * MIDN) / 256, 256>>>(b1);

    // 5) W2 GEMM (125 blocks; ldb=3129 odd -> scalar B path) + reduce
    gemm128<<<dim3(25, Z2), 256>>>(h, W2, W2, 1 << 30, outpart, NANS, MIDN, NANS, 0);
    reduce_out<<<(BQ * NANS + 255) / 256, 256>>>(b2, out);
}

// round 8
// speedup vs baseline: 1.9057x; 1.1658x over previous
#include <cuda_runtime.h>
#include <cuda_bf16.h>
#include <math.h>
#include <stdint.h>

#define HH      512
#define BQ      128
#define MIDN    2048
#define NANS    3129
#define W2PAD   3200
#define NNODES  131072
#define NEDGES  262144

#define SEGS    8
#define ZQ      16     // split-K for fused q projection
#define Z1      8      // split-K for W1
#define Z2      5      // split-K for W2

// ---------------- scratch (static __device__, no allocation) ----------------
__device__ float g_poolpart[3 * SEGS * BQ * HH];
__device__ int   g_cnt[3 * BQ];
__device__ float g_qpart[ZQ * BQ * 1024];
__device__ float g_h0[BQ * 1024];
__device__ float g_h1part[Z1 * BQ * MIDN];
__device__ float g_h[BQ * MIDN];
__device__ float g_outpart[Z2 * BQ * W2PAD];
// preconverted weights: k-pair-packed u32 [K/2][NPAD], hi and lo bf16 planes
__device__ uint32_t g_qWhi[512 * 1024];
__device__ uint32_t g_qWlo[512 * 1024];
__device__ uint32_t g_W1hi[512 * MIDN];
__device__ uint32_t g_W1lo[512 * MIDN];
__device__ uint32_t g_W2hi[1024 * W2PAD];
__device__ uint32_t g_W2lo[1024 * W2PAD];

// ---------------- weight preconvert: fp32 -> packed bf16 hi/lo --------------
// out[k2 * NPAD + colOff + j] = pack(bf16(W[2k2][j]), bf16(W[2k2+1][j]))
__global__ __launch_bounds__(256) void convW(const float* __restrict__ src,
                                             int N, int colOff, int NPAD,
                                             uint32_t* __restrict__ hi,
                                             uint32_t* __restrict__ lo,
                                             int Nsec, int tot) {
    int idx = blockIdx.x * 256 + threadIdx.x;
    if (idx >= tot) return;
    int k2 = idx / Nsec, j = idx - k2 * Nsec;
    float x0 = (j < N) ? src[(size_t)(2 * k2) * N + j] : 0.f;
    float x1 = (j < N) ? src[(size_t)(2 * k2 + 1) * N + j] : 0.f;
    __nv_bfloat16 h0 = __float2bfloat16_rn(x0);
    __nv_bfloat16 h1 = __float2bfloat16_rn(x1);
    __nv_bfloat16 l0 = __float2bfloat16_rn(x0 - __bfloat162float(h0));
    __nv_bfloat16 l1 = __float2bfloat16_rn(x1 - __bfloat162float(h1));
    __nv_bfloat162 hp(h0, h1), lp(l0, l1);
    size_t o = (size_t)k2 * NPAD + colOff + j;
    hi[o] = *(uint32_t*)&hp;
    lo[o] = *(uint32_t*)&lp;
}

// ---------------- bf16 mma.sync GEMM, 3-term fp32-faithful ------------------
// C_part[z] = A[128, Kslice] @ W[Kslice, NPAD-tile]; A fp32 row-major (lda),
// W packed hi/lo. CTA tile 128x128, 8 warps (2x4), warp tile 64x32, K-chunk 32.
__device__ __forceinline__ void mma_bf16(float* c, const uint32_t* a,
                                         uint32_t b0, uint32_t b1) {
    asm volatile("mma.sync.aligned.m16n8k16.row.col.f32.bf16.bf16.f32 "
                 "{%0,%1,%2,%3}, {%4,%5,%6,%7}, {%8,%9}, {%0,%1,%2,%3};"
                 : "+f"(c[0]), "+f"(c[1]), "+f"(c[2]), "+f"(c[3])
                 : "r"(a[0]), "r"(a[1]), "r"(a[2]), "r"(a[3]), "r"(b0), "r"(b1));
}

__global__ __launch_bounds__(256) void gemm_mma(const float* __restrict__ A, int lda,
                                                const uint32_t* __restrict__ BhiG,
                                                const uint32_t* __restrict__ BloG,
                                                int NPAD, float* __restrict__ Cpart,
                                                int K) {
    __shared__ __align__(16) __nv_bfloat16 Ah[128][40];
    __shared__ __align__(16) __nv_bfloat16 Al[128][40];
    __shared__ __align__(16) uint32_t Bh[16][136];
    __shared__ __align__(16) uint32_t Bl[16][136];

    const int tid = threadIdx.x, wid = tid >> 5, lane = tid & 31;
    const int wm = (wid >> 2) * 64, wn = (wid & 3) * 32;
    const int lr = lane >> 2, lc = lane & 3;

    const int z = blockIdx.y, Z = gridDim.y;
    const int chunks = K >> 5;
    const int c0 = chunks * z / Z, c1 = chunks * (z + 1) / Z;
    const int n0 = blockIdx.x * 128;

    float acc[4][4][4];
#pragma unroll
    for (int i = 0; i < 4; ++i)
#pragma unroll
        for (int j = 0; j < 4; ++j)
#pragma unroll
            for (int k = 0; k < 4; ++k) acc[i][j][k] = 0.f;

    const uint32_t* Au = (const uint32_t*)Ah;   // [128][20]
    const uint32_t* Alu = (const uint32_t*)Al;

    for (int c = c0; c < c1; ++c) {
        const int k0 = c << 5;

        // A: 128 x 32 fp32 -> bf16 hi/lo (1024 float4, 4 per thread)
#pragma unroll
        for (int it = 0; it < 4; ++it) {
            int q = tid + it * 256;
            int r = q >> 3, cc = (q & 7) << 2;
            float4 v = *(const float4*)(A + (size_t)r * lda + k0 + cc);
            __nv_bfloat16 h0 = __float2bfloat16_rn(v.x);
            __nv_bfloat16 h1 = __float2bfloat16_rn(v.y);
            __nv_bfloat16 h2 = __float2bfloat16_rn(v.z);
            __nv_bfloat16 h3 = __float2bfloat16_rn(v.w);
            __nv_bfloat162 hp0(h0, h1), hp1(h2, h3);
            __nv_bfloat162 lp0(__float2bfloat16_rn(v.x - __bfloat162float(h0)),
                               __float2bfloat16_rn(v.y - __bfloat162float(h1)));
            __nv_bfloat162 lp1(__float2bfloat16_rn(v.z - __bfloat162float(h2)),
                               __float2bfloat16_rn(v.w - __bfloat162float(h3)));
            *(uint2*)&Ah[r][cc] = make_uint2(*(uint32_t*)&hp0, *(uint32_t*)&hp1);
            *(uint2*)&Al[r][cc] = make_uint2(*(uint32_t*)&lp0, *(uint32_t*)&lp1);
        }
        // B: 16 k2-rows x 128 cols u32, hi+lo (512 uint4, 2 per thread)
        const int k20 = k0 >> 1;
#pragma unroll
        for (int it = 0; it < 2; ++it) {
            int q = tid + it * 256;
            int r = q >> 5, cc = (q & 31) << 2;
            size_t go = (size_t)(k20 + r) * NPAD + n0 + cc;
            *(uint4*)&Bh[r][cc] = *(const uint4*)(BhiG + go);
            *(uint4*)&Bl[r][cc] = *(const uint4*)(BloG + go);
        }
        __syncthreads();

#pragma unroll
        for (int ks = 0; ks < 2; ++ks) {
            const int kh = ks * 8;   // u32 k2 offset within chunk
            uint32_t ah[4][4], al[4][4];
#pragma unroll
            for (int mi = 0; mi < 4; ++mi) {
                int r0 = wm + mi * 16 + lr;
                ah[mi][0] = Au[r0 * 20 + kh + lc];
                ah[mi][1] = Au[(r0 + 8) * 20 + kh + lc];
                ah[mi][2] = Au[r0 * 20 + kh + 4 + lc];
                ah[mi][3] = Au[(r0 + 8) * 20 + kh + 4 + lc];
                al[mi][0] = Alu[r0 * 20 + kh + lc];
                al[mi][1] = Alu[(r0 + 8) * 20 + kh + lc];
                al[mi][2] = Alu[r0 * 20 + kh + 4 + lc];
                al[mi][3] = Alu[(r0 + 8) * 20 + kh + 4 + lc];
            }
            uint32_t bh[4][2], bl[4][2];
#pragma unroll
            for (int ni = 0; ni < 4; ++ni) {
                int nn = wn + ni * 8 + lr;
                bh[ni][0] = Bh[kh + lc][nn];
                bh[ni][1] = Bh[kh + 4 + lc][nn];
                bl[ni][0] = Bl[kh + lc][nn];
                bl[ni][1] = Bl[kh + 4 + lc][nn];
            }
#pragma unroll
            for (int mi = 0; mi < 4; ++mi)
#pragma unroll
                for (int ni = 0; ni < 4; ++ni) {
                    mma_bf16(acc[mi][ni], ah[mi], bh[ni][0], bh[ni][1]);
                    mma_bf16(acc[mi][ni], ah[mi], bl[ni][0], bl[ni][1]);
                    mma_bf16(acc[mi][ni], al[mi], bh[ni][0], bh[ni][1]);
                }
        }
        __syncthreads();
    }

    // epilogue: scatter accumulators to padded partial buffer
#pragma unroll
    for (int mi = 0; mi < 4; ++mi)
#pragma unroll
        for (int ni = 0; ni < 4; ++ni) {
            int row = wm + mi * 16 + lr;
            int col = n0 + wn + ni * 8 + lc * 2;
            float* Cp = Cpart + ((size_t)z * 128 + row) * NPAD + col;
            *(float2*)Cp = make_float2(acc[mi][ni][0], acc[mi][ni][1]);
            *(float2*)(Cp + (size_t)8 * NPAD) = make_float2(acc[mi][ni][2], acc[mi][ni][3]);
        }
}

// ---------------- fused segment-sum partials --------------------------------
__global__ __launch_bounds__(128) void seg_part(const float* __restrict__ f0,
                                                const float* __restrict__ f1,
                                                const float* __restrict__ f2,
                                                const int* __restrict__ sg0,
                                                const int* __restrict__ sg1,
                                                const int* __restrict__ sg2) {
    int arr = blockIdx.z;
    const float* feat = (arr == 0) ? f0 : (arr == 1) ? f1 : f2;
    const int*   seg  = (arr == 0) ? sg0 : (arr == 1) ? sg1 : sg2;
    int n = (arr == 2) ? NEDGES : NNODES;
    int b = blockIdx.y, s = blockIdx.x;

    int lo = 0, hi = n;
    while (lo < hi) { int m = (lo + hi) >> 1; if (seg[m] < b) lo = m + 1; else hi = m; }
    int st0 = lo; hi = n;
    while (lo < hi) { int m = (lo + hi) >> 1; if (seg[m] < b + 1) lo = m + 1; else hi = m; }
    int cnt = lo - st0;
    int r0 = st0 + (int)((long long)cnt * s / SEGS);
    int r1 = st0 + (int)((long long)cnt * (s + 1) / SEGS);

    const float4* p = (const float4*)feat + (size_t)r0 * 128 + threadIdx.x;
    float4 a0 = {0,0,0,0}, a1 = a0, a2 = a0, a3 = a0, a4 = a0, a5 = a0, a6 = a0, a7 = a0;
    int r = r0;
    for (; r + 8 <= r1; r += 8) {
        float4 v0 = p[0*128], v1 = p[1*128], v2 = p[2*128], v3 = p[3*128];
        float4 v4 = p[4*128], v5 = p[5*128], v6 = p[6*128], v7 = p[7*128];
        a0.x+=v0.x; a0.y+=v0.y; a0.z+=v0.z; a0.w+=v0.w;
        a1.x+=v1.x; a1.y+=v1.y; a1.z+=v1.z; a1.w+=v1.w;
        a2.x+=v2.x; a2.y+=v2.y; a2.z+=v2.z; a2.w+=v2.w;
        a3.x+=v3.x; a3.y+=v3.y; a3.z+=v3.z; a3.w+=v3.w;
        a4.x+=v4.x; a4.y+=v4.y; a4.z+=v4.z; a4.w+=v4.w;
        a5.x+=v5.x; a5.y+=v5.y; a5.z+=v5.z; a5.w+=v5.w;
        a6.x+=v6.x; a6.y+=v6.y; a6.z+=v6.z; a6.w+=v6.w;
        a7.x+=v7.x; a7.y+=v7.y; a7.z+=v7.z; a7.w+=v7.w;
        p += 8 * 128;
    }
    for (; r < r1; ++r) {
        float4 v = p[0];
        a0.x+=v.x; a0.y+=v.y; a0.z+=v.z; a0.w+=v.w;
        p += 128;
    }
    float4 t;
    t.x = ((a0.x+a1.x)+(a2.x+a3.x)) + ((a4.x+a5.x)+(a6.x+a7.x));
    t.y = ((a0.y+a1.y)+(a2.y+a3.y)) + ((a4.y+a5.y)+(a6.y+a7.y));
    t.z = ((a0.z+a1.z)+(a2.z+a3.z)) + ((a4.z+a5.z)+(a6.z+a7.z));
    t.w = ((a0.w+a1.w)+(a2.w+a3.w)) + ((a4.w+a5.w)+(a6.w+a7.w));
    float4* outp = (float4*)g_poolpart + (size_t)((arr * SEGS + s) * BQ + b) * 128 + threadIdx.x;
    *outp = t;
}

__global__ void count_seg(const int* __restrict__ sg0, const int* __restrict__ sg1,
                          const int* __restrict__ sg2) {
    int t = threadIdx.x;
    if (t >= 384) return;
    int arr = t >> 7, b = t & 127;
    const int* seg = (arr == 0) ? sg0 : (arr == 1) ? sg1 : sg2;
    int n = (arr == 2) ? NEDGES : NNODES;
    int lo = 0, hi = n;
    while (lo < hi) { int m = (lo + hi) >> 1; if (seg[m] < b) lo = m + 1; else hi = m; }
    int s0 = lo; hi = n;
    while (lo < hi) { int m = (lo + hi) >> 1; if (seg[m] < b + 1) lo = m + 1; else hi = m; }
    int c = lo - s0;
    g_cnt[t] = (c < 1) ? 1 : c;
}

// ---------------- assemble h0 ------------------------------------------------
__global__ __launch_bounds__(256) void build_h0(const float* __restrict__ bqe,
                                                const float* __restrict__ bqn) {
    int idx = blockIdx.x * 256 + threadIdx.x;   // 128*1024
    int b = idx >> 10, j = idx & 1023;
    float qs = 0.f;
#pragma unroll
    for (int z = 0; z < ZQ; ++z) qs += g_qpart[(size_t)z * (BQ * 1024) + idx];
    float r;
    if (j < 512) {
        float pe = 0.f;
#pragma unroll
        for (int s = 0; s < SEGS; ++s)
            pe += g_poolpart[(size_t)((2 * SEGS + s) * BQ + b) * HH + j];
        r = 2.f * (qs + bqe[j] + pe / (float)g_cnt[2 * BQ + b]);
    } else {
        int jj = j - 512;
        float p0 = 0.f, p1 = 0.f;
#pragma unroll
        for (int s = 0; s < SEGS; ++s) {
            p0 += g_poolpart[(size_t)((0 * SEGS + s) * BQ + b) * HH + jj];
            p1 += g_poolpart[(size_t)((1 * SEGS + s) * BQ + b) * HH + jj];
        }
        r = 2.f * (qs + bqn[jj]) + p0 / (float)g_cnt[b] + p1 / (float)g_cnt[BQ + b];
    }
    g_h0[idx] = r;
}

// ---------------- reduce split-K + bias + elu -------------------------------
__global__ __launch_bounds__(256) void reduce_elu(const float* __restrict__ b1) {
    int idx = blockIdx.x * 256 + threadIdx.x;   // 128*2048
    float s = b1[idx & (MIDN - 1)];
#pragma unroll
    for (int z = 0; z < Z1; ++z) s += g_h1part[(size_t)z * (BQ * MIDN) + idx];
    g_h[idx] = (s > 0.f) ? s : expm1f(s);
}

// ---------------- reduce split-K (padded) + bias -> output ------------------
__global__ __launch_bounds__(256) void reduce_out(const float* __restrict__ b2,
                                                  float* __restrict__ out) {
    int idx = blockIdx.x * 256 + threadIdx.x;
    if (idx >= BQ * NANS) return;
    int b = idx / NANS, n = idx - b * NANS;
    float s = b2[n];
#pragma unroll
    for (int z = 0; z < Z2; ++z) s += g_outpart[((size_t)z * BQ + b) * W2PAD + n];
    out[idx] = s;
}

// ---------------- launcher ---------------------------------------------------
extern "C" void kernel_launch(void* const* d_in, const int* in_sizes, int n_in,
                              void* d_out, int out_size) {
    const float* question      = (const float*)d_in[0];
    const float* img_node_feat = (const float*)d_in[1];
    const float* kg_node_feat  = (const float*)d_in[2];
    const float* img_edge_feat = (const float*)d_in[3];
    const int*   img_node_seg  = (const int*)d_in[5];
    const int*   kg_node_seg   = (const int*)d_in[6];
    const int*   img_edge_seg  = (const int*)d_in[7];
    const float* Wqe = (const float*)d_in[9];
    const float* bqe = (const float*)d_in[10];
    const float* Wqn = (const float*)d_in[11];
    const float* bqn = (const float*)d_in[12];
    const float* W1  = (const float*)d_in[13];
    const float* b1  = (const float*)d_in[14];
    const float* W2  = (const float*)d_in[15];
    const float* b2  = (const float*)d_in[16];
    float* out = (float*)d_out;

    float *qpart, *h0, *h1part, *h, *outpart;
    uint32_t *qWhi, *qWlo, *W1hi, *W1lo, *W2hi, *W2lo;
    cudaGetSymbolAddress((void**)&qpart,   g_qpart);
    cudaGetSymbolAddress((void**)&h0,      g_h0);
    cudaGetSymbolAddress((void**)&h1part,  g_h1part);
    cudaGetSymbolAddress((void**)&h,       g_h);
    cudaGetSymbolAddress((void**)&outpart, g_outpart);
    cudaGetSymbolAddress((void**)&qWhi, g_qWhi);
    cudaGetSymbolAddress((void**)&qWlo, g_qWlo);
    cudaGetSymbolAddress((void**)&W1hi, g_W1hi);
    cudaGetSymbolAddress((void**)&W1lo, g_W1lo);
    cudaGetSymbolAddress((void**)&W2hi, g_W2hi);
    cudaGetSymbolAddress((void**)&W2lo, g_W2lo);

    // 0) weight preconvert (fp32 -> packed bf16 hi/lo)
    convW<<<(1024 * W2PAD + 255) / 256, 256>>>(W2, NANS, 0, W2PAD, W2hi, W2lo, W2PAD, 1024 * W2PAD);
    convW<<<(512 * MIDN + 255) / 256, 256>>>(W1, MIDN, 0, MIDN, W1hi, W1lo, MIDN, 512 * MIDN);
    convW<<<(512 * 512 + 255) / 256, 256>>>(Wqe, 512, 0, 1024, qWhi, qWlo, 512, 512 * 512);
    convW<<<(512 * 512 + 255) / 256, 256>>>(Wqn, 512, 512, 1024, qWhi, qWlo, 512, 512 * 512);

    // 1) pools + counts
    seg_part<<<dim3(SEGS, BQ, 3), 128>>>(img_node_feat, kg_node_feat, img_edge_feat,
                                         img_node_seg, kg_node_seg, img_edge_seg);
    count_seg<<<1, 384>>>(img_node_seg, kg_node_seg, img_edge_seg);

    // 2) fused q projection: [Wqe|Wqn] packed side by side, 8x16 = 128 CTAs
    gemm_mma<<<dim3(8, ZQ), 256>>>(question, 1024, qWhi, qWlo, 1024, qpart, 1024);

    // 3) assemble h0
    build_h0<<<(BQ * 1024) / 256, 256>>>(bqe, bqn);

    // 4) W1: 16x8 = 128 CTAs; + elu reduce
    gemm_mma<<<dim3(16, Z1), 256>>>(h0, 1024, W1hi, W1lo, MIDN, h1part, 1024);
    reduce_elu<<<(BQ * MIDN) / 256, 256>>>(b1);

    // 5) W2: 25x5 = 125 CTAs; + reduce
    gemm_mma<<<dim3(25, Z2), 256>>>(h, MIDN, W2hi, W2lo, W2PAD, outpart, MIDN);
    reduce_out<<<(BQ * NANS + 255) / 256, 256>>>(b2, out);
}

// round 9
// speedup vs baseline: 2.0852x; 1.0942x over previous
#include <cuda_runtime.h>
#include <cuda_bf16.h>
#include <math.h>
#include <stdint.h>

#define HH      512
#define BQ      128
#define MIDN    2048
#define NANS    3129
#define W2PAD   3200
#define NNODES  131072
#define NEDGES  262144

#define SEGS    8
#define ZQ      16     // split-K for fused q projection
#define Z1      8      // split-K for W1
#define Z2      5      // split-K for W2

// conversion item ranges (one item = one packed u32 output in hi+lo planes)
#define CITEMS_W2  (1024 * W2PAD)
#define CITEMS_W1  (512 * MIDN)
#define CITEMS_QE  (512 * 512)
#define CR0        CITEMS_W2
#define CR1        (CR0 + CITEMS_W1)
#define CR2        (CR1 + CITEMS_QE)
#define CR3        (CR2 + CITEMS_QE)

// ---------------- scratch (static __device__, no allocation) ----------------
__device__ float g_poolpart[3 * SEGS * BQ * HH];
__device__ int   g_cnt[3 * BQ];
__device__ float g_qpart[ZQ * BQ * 1024];
__device__ float g_h0[BQ * 1024];
__device__ float g_h1part[Z1 * BQ * MIDN];
__device__ float g_h[BQ * MIDN];
__device__ float g_outpart[Z2 * BQ * W2PAD];
// preconverted weights: k-pair-packed u32 [K/2][NPAD], hi and lo bf16 planes
__device__ uint32_t g_qWhi[512 * 1024];
__device__ uint32_t g_qWlo[512 * 1024];
__device__ uint32_t g_W1hi[512 * MIDN];
__device__ uint32_t g_W1lo[512 * MIDN];
__device__ uint32_t g_W2hi[1024 * W2PAD];
__device__ uint32_t g_W2lo[1024 * W2PAD];

// ---------------- conversion helper -----------------------------------------
__device__ __forceinline__ void conv_item(const float* __restrict__ src, int N,
                                          int NPAD, int colOff,
                                          uint32_t* __restrict__ hi,
                                          uint32_t* __restrict__ lo,
                                          int k2, int j) {
    float x0 = 0.f, x1 = 0.f;
    if (j < N) {
        x0 = __ldcs(src + (size_t)(2 * k2) * N + j);
        x1 = __ldcs(src + (size_t)(2 * k2 + 1) * N + j);
    }
    __nv_bfloat16 h0 = __float2bfloat16_rn(x0);
    __nv_bfloat16 h1 = __float2bfloat16_rn(x1);
    __nv_bfloat16 l0 = __float2bfloat16_rn(x0 - __bfloat162float(h0));
    __nv_bfloat16 l1 = __float2bfloat16_rn(x1 - __bfloat162float(h1));
    __nv_bfloat162 hp(h0, h1), lp(l0, l1);
    size_t o = (size_t)k2 * NPAD + colOff + j;
    hi[o] = *(uint32_t*)&hp;
    lo[o] = *(uint32_t*)&lp;
}

// ---------------- mega kernel: 3 pool planes + 1 conversion plane -----------
// z in {0,1,2}: segment-sum partials (x = row-split, y = batch).
// z == 3     : grid-stride weight conversion over all 4 weight matrices.
__global__ __launch_bounds__(128) void pool_conv(const float* __restrict__ f0,
                                                 const float* __restrict__ f1,
                                                 const float* __restrict__ f2,
                                                 const int* __restrict__ sg0,
                                                 const int* __restrict__ sg1,
                                                 const int* __restrict__ sg2,
                                                 const float* __restrict__ Wqe,
                                                 const float* __restrict__ Wqn,
                                                 const float* __restrict__ W1,
                                                 const float* __restrict__ W2) {
    int arr = blockIdx.z;
    if (arr == 3) {
        int t = (blockIdx.y * SEGS + blockIdx.x) * 128 + threadIdx.x;
        const int stride = SEGS * BQ * 128;
        for (int i = t; i < CR3; i += stride) {
            if (i < CR0) {
                int k2 = i / W2PAD, j = i - k2 * W2PAD;
                conv_item(W2, NANS, W2PAD, 0, g_W2hi, g_W2lo, k2, j);
            } else if (i < CR1) {
                int q = i - CR0;
                int k2 = q >> 11, j = q & (MIDN - 1);
                conv_item(W1, MIDN, MIDN, 0, g_W1hi, g_W1lo, k2, j);
            } else if (i < CR2) {
                int q = i - CR1;
                int k2 = q >> 9, j = q & 511;
                conv_item(Wqe, 512, 1024, 0, g_qWhi, g_qWlo, k2, j);
            } else {
                int q = i - CR2;
                int k2 = q >> 9, j = q & 511;
                conv_item(Wqn, 512, 1024, 512, g_qWhi, g_qWlo, k2, j);
            }
        }
        return;
    }

    const float* feat = (arr == 0) ? f0 : (arr == 1) ? f1 : f2;
    const int*   seg  = (arr == 0) ? sg0 : (arr == 1) ? sg1 : sg2;
    int n = (arr == 2) ? NEDGES : NNODES;
    int b = blockIdx.y, s = blockIdx.x;

    int lo = 0, hi = n;
    while (lo < hi) { int m = (lo + hi) >> 1; if (seg[m] < b) lo = m + 1; else hi = m; }
    int st0 = lo; hi = n;
    while (lo < hi) { int m = (lo + hi) >> 1; if (seg[m] < b + 1) lo = m + 1; else hi = m; }
    int cnt = lo - st0;
    int r0 = st0 + (int)((long long)cnt * s / SEGS);
    int r1 = st0 + (int)((long long)cnt * (s + 1) / SEGS);

    const float4* p = (const float4*)feat + (size_t)r0 * 128 + threadIdx.x;
    float4 a0 = {0,0,0,0}, a1 = a0, a2 = a0, a3 = a0, a4 = a0, a5 = a0, a6 = a0, a7 = a0;
    int r = r0;
    for (; r + 8 <= r1; r += 8) {
        float4 v0 = __ldcs(p + 0*128), v1 = __ldcs(p + 1*128);
        float4 v2 = __ldcs(p + 2*128), v3 = __ldcs(p + 3*128);
        float4 v4 = __ldcs(p + 4*128), v5 = __ldcs(p + 5*128);
        float4 v6 = __ldcs(p + 6*128), v7 = __ldcs(p + 7*128);
        a0.x+=v0.x; a0.y+=v0.y; a0.z+=v0.z; a0.w+=v0.w;
        a1.x+=v1.x; a1.y+=v1.y; a1.z+=v1.z; a1.w+=v1.w;
        a2.x+=v2.x; a2.y+=v2.y; a2.z+=v2.z; a2.w+=v2.w;
        a3.x+=v3.x; a3.y+=v3.y; a3.z+=v3.z; a3.w+=v3.w;
        a4.x+=v4.x; a4.y+=v4.y; a4.z+=v4.z; a4.w+=v4.w;
        a5.x+=v5.x; a5.y+=v5.y; a5.z+=v5.z; a5.w+=v5.w;
        a6.x+=v6.x; a6.y+=v6.y; a6.z+=v6.z; a6.w+=v6.w;
        a7.x+=v7.x; a7.y+=v7.y; a7.z+=v7.z; a7.w+=v7.w;
        p += 8 * 128;
    }
    for (; r < r1; ++r) {
        float4 v = __ldcs(p);
        a0.x+=v.x; a0.y+=v.y; a0.z+=v.z; a0.w+=v.w;
        p += 128;
    }
    float4 t;
    t.x = ((a0.x+a1.x)+(a2.x+a3.x)) + ((a4.x+a5.x)+(a6.x+a7.x));
    t.y = ((a0.y+a1.y)+(a2.y+a3.y)) + ((a4.y+a5.y)+(a6.y+a7.y));
    t.z = ((a0.z+a1.z)+(a2.z+a3.z)) + ((a4.z+a5.z)+(a6.z+a7.z));
    t.w = ((a0.w+a1.w)+(a2.w+a3.w)) + ((a4.w+a5.w)+(a6.w+a7.w));
    float4* outp = (float4*)g_poolpart + (size_t)((arr * SEGS + s) * BQ + b) * 128 + threadIdx.x;
    *outp = t;
}

// ---------------- bf16 mma.sync GEMM, 3-term fp32-faithful ------------------
__device__ __forceinline__ void mma_bf16(float* c, const uint32_t* a,
                                         uint32_t b0, uint32_t b1) {
    asm volatile("mma.sync.aligned.m16n8k16.row.col.f32.bf16.bf16.f32 "
                 "{%0,%1,%2,%3}, {%4,%5,%6,%7}, {%8,%9}, {%0,%1,%2,%3};"
                 : "+f"(c[0]), "+f"(c[1]), "+f"(c[2]), "+f"(c[3])
                 : "r"(a[0]), "r"(a[1]), "r"(a[2]), "r"(a[3]), "r"(b0), "r"(b1));
}

__global__ __launch_bounds__(256) void gemm_mma(const float* __restrict__ A, int lda,
                                                const uint32_t* __restrict__ BhiG,
                                                const uint32_t* __restrict__ BloG,
                                                int NPAD, float* __restrict__ Cpart,
                                                int K) {
    __shared__ __align__(16) __nv_bfloat16 Ah[128][40];
    __shared__ __align__(16) __nv_bfloat16 Al[128][40];
    __shared__ __align__(16) uint32_t Bh[16][136];
    __shared__ __align__(16) uint32_t Bl[16][136];

    const int tid = threadIdx.x, wid = tid >> 5, lane = tid & 31;
    const int wm = (wid >> 2) * 64, wn = (wid & 3) * 32;
    const int lr = lane >> 2, lc = lane & 3;

    const int z = blockIdx.y, Z = gridDim.y;
    const int chunks = K >> 5;
    const int c0 = chunks * z / Z, c1 = chunks * (z + 1) / Z;
    const int n0 = blockIdx.x * 128;

    float acc[4][4][4];
#pragma unroll
    for (int i = 0; i < 4; ++i)
#pragma unroll
        for (int j = 0; j < 4; ++j)
#pragma unroll
            for (int k = 0; k < 4; ++k) acc[i][j][k] = 0.f;

    const uint32_t* Au = (const uint32_t*)Ah;   // [128][20]
    const uint32_t* Alu = (const uint32_t*)Al;

    for (int c = c0; c < c1; ++c) {
        const int k0 = c << 5;
#pragma unroll
        for (int it = 0; it < 4; ++it) {
            int q = tid + it * 256;
            int r = q >> 3, cc = (q & 7) << 2;
            float4 v = *(const float4*)(A + (size_t)r * lda + k0 + cc);
            __nv_bfloat16 h0 = __float2bfloat16_rn(v.x);
            __nv_bfloat16 h1 = __float2bfloat16_rn(v.y);
            __nv_bfloat16 h2 = __float2bfloat16_rn(v.z);
            __nv_bfloat16 h3 = __float2bfloat16_rn(v.w);
            __nv_bfloat162 hp0(h0, h1), hp1(h2, h3);
            __nv_bfloat162 lp0(__float2bfloat16_rn(v.x - __bfloat162float(h0)),
                               __float2bfloat16_rn(v.y - __bfloat162float(h1)));
            __nv_bfloat162 lp1(__float2bfloat16_rn(v.z - __bfloat162float(h2)),
                               __float2bfloat16_rn(v.w - __bfloat162float(h3)));
            *(uint2*)&Ah[r][cc] = make_uint2(*(uint32_t*)&hp0, *(uint32_t*)&hp1);
            *(uint2*)&Al[r][cc] = make_uint2(*(uint32_t*)&lp0, *(uint32_t*)&lp1);
        }
        const int k20 = k0 >> 1;
#pragma unroll
        for (int it = 0; it < 2; ++it) {
            int q = tid + it * 256;
            int r = q >> 5, cc = (q & 31) << 2;
            size_t go = (size_t)(k20 + r) * NPAD + n0 + cc;
            *(uint4*)&Bh[r][cc] = *(const uint4*)(BhiG + go);
            *(uint4*)&Bl[r][cc] = *(const uint4*)(BloG + go);
        }
        __syncthreads();

#pragma unroll
        for (int ks = 0; ks < 2; ++ks) {
            const int kh = ks * 8;
            uint32_t ah[4][4], al[4][4];
#pragma unroll
            for (int mi = 0; mi < 4; ++mi) {
                int r0 = wm + mi * 16 + lr;
                ah[mi][0] = Au[r0 * 20 + kh + lc];
                ah[mi][1] = Au[(r0 + 8) * 20 + kh + lc];
                ah[mi][2] = Au[r0 * 20 + kh + 4 + lc];
                ah[mi][3] = Au[(r0 + 8) * 20 + kh + 4 + lc];
                al[mi][0] = Alu[r0 * 20 + kh + lc];
                al[mi][1] = Alu[(r0 + 8) * 20 + kh + lc];
                al[mi][2] = Alu[r0 * 20 + kh + 4 + lc];
                al[mi][3] = Alu[(r0 + 8) * 20 + kh + 4 + lc];
            }
            uint32_t bh[4][2], bl[4][2];
#pragma unroll
            for (int ni = 0; ni < 4; ++ni) {
                int nn = wn + ni * 8 + lr;
                bh[ni][0] = Bh[kh + lc][nn];
                bh[ni][1] = Bh[kh + 4 + lc][nn];
                bl[ni][0] = Bl[kh + lc][nn];
                bl[ni][1] = Bl[kh + 4 + lc][nn];
            }
#pragma unroll
            for (int mi = 0; mi < 4; ++mi)
#pragma unroll
                for (int ni = 0; ni < 4; ++ni) {
                    mma_bf16(acc[mi][ni], ah[mi], bh[ni][0], bh[ni][1]);
                    mma_bf16(acc[mi][ni], ah[mi], bl[ni][0], bl[ni][1]);
                    mma_bf16(acc[mi][ni], al[mi], bh[ni][0], bh[ni][1]);
                }
        }
        __syncthreads();
    }

#pragma unroll
    for (int mi = 0; mi < 4; ++mi)
#pragma unroll
        for (int ni = 0; ni < 4; ++ni) {
            int row = wm + mi * 16 + lr;
            int col = n0 + wn + ni * 8 + lc * 2;
            float* Cp = Cpart + ((size_t)z * 128 + row) * NPAD + col;
            *(float2*)Cp = make_float2(acc[mi][ni][0], acc[mi][ni][1]);
            *(float2*)(Cp + (size_t)8 * NPAD) = make_float2(acc[mi][ni][2], acc[mi][ni][3]);
        }
}

// ---------------- segment counts --------------------------------------------
__global__ void count_seg(const int* __restrict__ sg0, const int* __restrict__ sg1,
                          const int* __restrict__ sg2) {
    int t = threadIdx.x;
    if (t >= 384) return;
    int arr = t >> 7, b = t & 127;
    const int* seg = (arr == 0) ? sg0 : (arr == 1) ? sg1 : sg2;
    int n = (arr == 2) ? NEDGES : NNODES;
    int lo = 0, hi = n;
    while (lo < hi) { int m = (lo + hi) >> 1; if (seg[m] < b) lo = m + 1; else hi = m; }
    int s0 = lo; hi = n;
    while (lo < hi) { int m = (lo + hi) >> 1; if (seg[m] < b + 1) lo = m + 1; else hi = m; }
    int c = lo - s0;
    g_cnt[t] = (c < 1) ? 1 : c;
}

// ---------------- assemble h0 ------------------------------------------------
__global__ __launch_bounds__(256) void build_h0(const float* __restrict__ bqe,
                                                const float* __restrict__ bqn) {
    int idx = blockIdx.x * 256 + threadIdx.x;   // 128*1024
    int b = idx >> 10, j = idx & 1023;
    float qs = 0.f;
#pragma unroll
    for (int z = 0; z < ZQ; ++z) qs += g_qpart[(size_t)z * (BQ * 1024) + idx];
    float r;
    if (j < 512) {
        float pe = 0.f;
#pragma unroll
        for (int s = 0; s < SEGS; ++s)
            pe += g_poolpart[(size_t)((2 * SEGS + s) * BQ + b) * HH + j];
        r = 2.f * (qs + bqe[j] + pe / (float)g_cnt[2 * BQ + b]);
    } else {
        int jj = j - 512;
        float p0 = 0.f, p1 = 0.f;
#pragma unroll
        for (int s = 0; s < SEGS; ++s) {
            p0 += g_poolpart[(size_t)((0 * SEGS + s) * BQ + b) * HH + jj];
            p1 += g_poolpart[(size_t)((1 * SEGS + s) * BQ + b) * HH + jj];
        }
        r = 2.f * (qs + bqn[jj]) + p0 / (float)g_cnt[b] + p1 / (float)g_cnt[BQ + b];
    }
    g_h0[idx] = r;
}

// ---------------- reduce split-K + bias + elu -------------------------------
__global__ __launch_bounds__(256) void reduce_elu(const float* __restrict__ b1) {
    int idx = blockIdx.x * 256 + threadIdx.x;   // 128*2048
    float s = b1[idx & (MIDN - 1)];
#pragma unroll
    for (int z = 0; z < Z1; ++z) s += g_h1part[(size_t)z * (BQ * MIDN) + idx];
    g_h[idx] = (s > 0.f) ? s : expm1f(s);
}

// ---------------- reduce split-K (padded) + bias -> output ------------------
__global__ __launch_bounds__(256) void reduce_out(const float* __restrict__ b2,
                                                  float* __restrict__ out) {
    int idx = blockIdx.x * 256 + threadIdx.x;
    if (idx >= BQ * NANS) return;
    int b = idx / NANS, n = idx - b * NANS;
    float s = b2[n];
#pragma unroll
    for (int z = 0; z < Z2; ++z) s += g_outpart[((size_t)z * BQ + b) * W2PAD + n];
    out[idx] = s;
}

// ---------------- launcher ---------------------------------------------------
extern "C" void kernel_launch(void* const* d_in, const int* in_sizes, int n_in,
                              void* d_out, int out_size) {
    const float* question      = (const float*)d_in[0];
    const float* img_node_feat = (const float*)d_in[1];
    const float* kg_node_feat  = (const float*)d_in[2];
    const float* img_edge_feat = (const float*)d_in[3];
    const int*   img_node_seg  = (const int*)d_in[5];
    const int*   kg_node_seg   = (const int*)d_in[6];
    const int*   img_edge_seg  = (const int*)d_in[7];
    const float* Wqe = (const float*)d_in[9];
    const float* bqe = (const float*)d_in[10];
    const float* Wqn = (const float*)d_in[11];
    const float* bqn = (const float*)d_in[12];
    const float* W1  = (const float*)d_in[13];
    const float* b1  = (const float*)d_in[14];
    const float* W2  = (const float*)d_in[15];
    const float* b2  = (const float*)d_in[16];
    float* out = (float*)d_out;

    float *qpart, *h0, *h1part, *h, *outpart;
    uint32_t *qWhi, *qWlo, *W1hi, *W1lo, *W2hi, *W2lo;
    cudaGetSymbolAddress((void**)&qpart,   g_qpart);
    cudaGetSymbolAddress((void**)&h0,      g_h0);
    cudaGetSymbolAddress((void**)&h1part,  g_h1part);
    cudaGetSymbolAddress((void**)&h,       g_h);
    cudaGetSymbolAddress((void**)&outpart, g_outpart);
    cudaGetSymbolAddress((void**)&qWhi, g_qWhi);
    cudaGetSymbolAddress((void**)&qWlo, g_qWlo);
    cudaGetSymbolAddress((void**)&W1hi, g_W1hi);
    cudaGetSymbolAddress((void**)&W1lo, g_W1lo);
    cudaGetSymbolAddress((void**)&W2hi, g_W2hi);
    cudaGetSymbolAddress((void**)&W2lo, g_W2lo);

    // 1) pools + ALL weight conversions in one launch (overlapped), + counts
    pool_conv<<<dim3(SEGS, BQ, 4), 128>>>(img_node_feat, kg_node_feat, img_edge_feat,
                                          img_node_seg, kg_node_seg, img_edge_seg,
                                          Wqe, Wqn, W1, W2);
    count_seg<<<1, 384>>>(img_node_seg, kg_node_seg, img_edge_seg);

    // 2) fused q projection: [Wqe|Wqn] packed side by side, 8x16 = 128 CTAs
    gemm_mma<<<dim3(8, ZQ), 256>>>(question, 1024, qWhi, qWlo, 1024, qpart, 1024);

    // 3) assemble h0
    build_h0<<<(BQ * 1024) / 256, 256>>>(bqe, bqn);

    // 4) W1: 16x8 = 128 CTAs; + elu reduce
    gemm_mma<<<dim3(16, Z1), 256>>>(h0, 1024, W1hi, W1lo, MIDN, h1part, 1024);
    reduce_elu<<<(BQ * MIDN) / 256, 256>>>(b1);

    // 5) W2: 25x5 = 125 CTAs; + reduce
    gemm_mma<<<dim3(25, Z2), 256>>>(h, MIDN, W2hi, W2lo, W2PAD, outpart, MIDN);
    reduce_out<<<(BQ * NANS + 255) / 256, 256>>>(b2, out);
}

// round 11
// speedup vs baseline: 2.2478x; 1.0780x over previous
#include <cuda_runtime.h>
#include <cuda_bf16.h>
#include <math.h>
#include <stdint.h>

#define HH      512
#define BQ      128
#define MIDN    2048
#define NANS    3129
#define W2PAD   3200
#define NNODES  131072
#define NEDGES  262144

#define SEGS    8
#define ZQ      16     // split-K for fused q projection
#define Z1      8      // split-K for W1
#define Z2      5      // split-K for W2

// ---------------- scratch (static __device__, no allocation) ----------------
__device__ float g_poolpart[3 * SEGS * BQ * HH];
__device__ float g_qpart[ZQ * BQ * 1024];
__device__ float g_h0[BQ * 1024];
__device__ float g_h1part[Z1 * BQ * MIDN];
__device__ float g_h[BQ * MIDN];
__device__ float g_outpart[Z2 * BQ * W2PAD];

// ---------------- pool: fused segment-sum partials (3 planes) ---------------
__global__ __launch_bounds__(128) void seg_part(const float* __restrict__ f0,
                                                const float* __restrict__ f1,
                                                const float* __restrict__ f2,
                                                const int* __restrict__ sg0,
                                                const int* __restrict__ sg1,
                                                const int* __restrict__ sg2) {
    int arr = blockIdx.z;
    const float* feat = (arr == 0) ? f0 : (arr == 1) ? f1 : f2;
    const int*   seg  = (arr == 0) ? sg0 : (arr == 1) ? sg1 : sg2;
    int n = (arr == 2) ? NEDGES : NNODES;
    int b = blockIdx.y, s = blockIdx.x;

    int lo = 0, hi = n;
    while (lo < hi) { int m = (lo + hi) >> 1; if (seg[m] < b) lo = m + 1; else hi = m; }
    int st0 = lo; hi = n;
    while (lo < hi) { int m = (lo + hi) >> 1; if (seg[m] < b + 1) lo = m + 1; else hi = m; }
    int cnt = lo - st0;
    int r0 = st0 + (int)((long long)cnt * s / SEGS);
    int r1 = st0 + (int)((long long)cnt * (s + 1) / SEGS);

    const float4* p = (const float4*)feat + (size_t)r0 * 128 + threadIdx.x;
    float4 a0 = {0,0,0,0}, a1 = a0, a2 = a0, a3 = a0, a4 = a0, a5 = a0, a6 = a0, a7 = a0;
    int r = r0;
    for (; r + 8 <= r1; r += 8) {
        float4 v0 = __ldcs(p + 0*128), v1 = __ldcs(p + 1*128);
        float4 v2 = __ldcs(p + 2*128), v3 = __ldcs(p + 3*128);
        float4 v4 = __ldcs(p + 4*128), v5 = __ldcs(p + 5*128);
        float4 v6 = __ldcs(p + 6*128), v7 = __ldcs(p + 7*128);
        a0.x+=v0.x; a0.y+=v0.y; a0.z+=v0.z; a0.w+=v0.w;
        a1.x+=v1.x; a1.y+=v1.y; a1.z+=v1.z; a1.w+=v1.w;
        a2.x+=v2.x; a2.y+=v2.y; a2.z+=v2.z; a2.w+=v2.w;
        a3.x+=v3.x; a3.y+=v3.y; a3.z+=v3.z; a3.w+=v3.w;
        a4.x+=v4.x; a4.y+=v4.y; a4.z+=v4.z; a4.w+=v4.w;
        a5.x+=v5.x; a5.y+=v5.y; a5.z+=v5.z; a5.w+=v5.w;
        a6.x+=v6.x; a6.y+=v6.y; a6.z+=v6.z; a6.w+=v6.w;
        a7.x+=v7.x; a7.y+=v7.y; a7.z+=v7.z; a7.w+=v7.w;
        p += 8 * 128;
    }
    for (; r < r1; ++r) {
        float4 v = __ldcs(p);
        a0.x+=v.x; a0.y+=v.y; a0.z+=v.z; a0.w+=v.w;
        p += 128;
    }
    float4 t;
    t.x = ((a0.x+a1.x)+(a2.x+a3.x)) + ((a4.x+a5.x)+(a6.x+a7.x));
    t.y = ((a0.y+a1.y)+(a2.y+a3.y)) + ((a4.y+a5.y)+(a6.y+a7.y));
    t.z = ((a0.z+a1.z)+(a2.z+a3.z)) + ((a4.z+a5.z)+(a6.z+a7.z));
    t.w = ((a0.w+a1.w)+(a2.w+a3.w)) + ((a4.w+a5.w)+(a6.w+a7.w));
    float4* outp = (float4*)g_poolpart + (size_t)((arr * SEGS + s) * BQ + b) * 128 + threadIdx.x;
    *outp = t;
}

// ---------------- bf16 mma.sync GEMM with FUSED fp32->hi/lo conversion ------
// C_part[z] = A[128,Kslice] @ W[Kslice, N-tile]; A fp32 row-major (lda),
// W fp32 row-major read directly (converted+packed in the B loader).
// B source selected per n-block from {B1,B2} at column split N1 (fused q proj).
__device__ __forceinline__ void mma_bf16(float* c, const uint32_t* a,
                                         uint32_t b0, uint32_t b1) {
    asm volatile("mma.sync.aligned.m16n8k16.row.col.f32.bf16.bf16.f32 "
                 "{%0,%1,%2,%3}, {%4,%5,%6,%7}, {%8,%9}, {%0,%1,%2,%3};"
                 : "+f"(c[0]), "+f"(c[1]), "+f"(c[2]), "+f"(c[3])
                 : "r"(a[0]), "r"(a[1]), "r"(a[2]), "r"(a[3]), "r"(b0), "r"(b1));
}

__global__ __launch_bounds__(256) void gemm_mma_f(const float* __restrict__ A, int lda,
                                                  const float* __restrict__ B1,
                                                  const float* __restrict__ B2, int N1,
                                                  int Nreal, int NPAD,
                                                  float* __restrict__ Cpart, int K) {
    __shared__ __align__(16) __nv_bfloat16 Ah[128][40];
    __shared__ __align__(16) __nv_bfloat16 Al[128][40];
    __shared__ __align__(16) uint32_t Bh[16][136];
    __shared__ __align__(16) uint32_t Bl[16][136];

    const int tid = threadIdx.x, wid = tid >> 5, lane = tid & 31;
    const int wm = (wid >> 2) * 64, wn = (wid & 3) * 32;
    const int lr = lane >> 2, lc = lane & 3;

    const int z = blockIdx.y, Z = gridDim.y;
    const int chunks = K >> 5;
    const int c0 = chunks * z / Z, c1 = chunks * (z + 1) / Z;
    const int n0 = blockIdx.x * 128;

    const float* W; int nb;
    if (n0 < N1) { W = B1; nb = n0; } else { W = B2; nb = n0 - N1; }
    const bool full = (nb + 128 <= Nreal) && ((Nreal & 3) == 0);

    float acc[4][4][4];
#pragma unroll
    for (int i = 0; i < 4; ++i)
#pragma unroll
        for (int j = 0; j < 4; ++j)
#pragma unroll
            for (int k = 0; k < 4; ++k) acc[i][j][k] = 0.f;

    const uint32_t* Au = (const uint32_t*)Ah;   // [128][20]
    const uint32_t* Alu = (const uint32_t*)Al;

    for (int c = c0; c < c1; ++c) {
        const int k0 = c << 5;

        // A: 128 x 32 fp32 -> bf16 hi/lo (1024 float4, 4 per thread)
#pragma unroll
        for (int it = 0; it < 4; ++it) {
            int q = tid + it * 256;
            int r = q >> 3, cc = (q & 7) << 2;
            float4 v = *(const float4*)(A + (size_t)r * lda + k0 + cc);
            __nv_bfloat16 h0 = __float2bfloat16_rn(v.x);
            __nv_bfloat16 h1 = __float2bfloat16_rn(v.y);
            __nv_bfloat16 h2 = __float2bfloat16_rn(v.z);
            __nv_bfloat16 h3 = __float2bfloat16_rn(v.w);
            __nv_bfloat162 hp0(h0, h1), hp1(h2, h3);
            __nv_bfloat162 lp0(__float2bfloat16_rn(v.x - __bfloat162float(h0)),
                               __float2bfloat16_rn(v.y - __bfloat162float(h1)));
            __nv_bfloat162 lp1(__float2bfloat16_rn(v.z - __bfloat162float(h2)),
                               __float2bfloat16_rn(v.w - __bfloat162float(h3)));
            *(uint2*)&Ah[r][cc] = make_uint2(*(uint32_t*)&hp0, *(uint32_t*)&hp1);
            *(uint2*)&Al[r][cc] = make_uint2(*(uint32_t*)&lp0, *(uint32_t*)&lp1);
        }

        // B: read fp32 rows 2k2/2k2+1 directly, convert+pack k-pairs in-loader
        const int k20 = k0 >> 1;
#pragma unroll
        for (int it = 0; it < 2; ++it) {
            int q = tid + it * 256;
            int r = q >> 5, cg = (q & 31) << 2;
            const float* p0 = W + (size_t)((k20 + r) * 2) * Nreal + nb + cg;
            const float* p1 = p0 + Nreal;
            float v0[4], v1[4];
            if (full) {
                float4 a4 = *(const float4*)p0;
                float4 b4 = *(const float4*)p1;
                v0[0] = a4.x; v0[1] = a4.y; v0[2] = a4.z; v0[3] = a4.w;
                v1[0] = b4.x; v1[1] = b4.y; v1[2] = b4.z; v1[3] = b4.w;
            } else {
#pragma unroll
                for (int j = 0; j < 4; ++j) {
                    bool in = (nb + cg + j) < Nreal;
                    v0[j] = in ? p0[j] : 0.f;
                    v1[j] = in ? p1[j] : 0.f;
                }
            }
            uint32_t hw[4], lw[4];
#pragma unroll
            for (int j = 0; j < 4; ++j) {
                __nv_bfloat16 h0 = __float2bfloat16_rn(v0[j]);
                __nv_bfloat16 h1 = __float2bfloat16_rn(v1[j]);
                __nv_bfloat162 hp(h0, h1);
                __nv_bfloat162 lp(__float2bfloat16_rn(v0[j] - __bfloat162float(h0)),
                                  __float2bfloat16_rn(v1[j] - __bfloat162float(h1)));
                hw[j] = *(uint32_t*)&hp;
                lw[j] = *(uint32_t*)&lp;
            }
            *(uint4*)&Bh[r][cg] = make_uint4(hw[0], hw[1], hw[2], hw[3]);
            *(uint4*)&Bl[r][cg] = make_uint4(lw[0], lw[1], lw[2], lw[3]);
        }
        __syncthreads();

#pragma unroll
        for (int ks = 0; ks < 2; ++ks) {
            const int kh = ks * 8;
            uint32_t ah[4][4], al[4][4];
#pragma unroll
            for (int mi = 0; mi < 4; ++mi) {
                int r0 = wm + mi * 16 + lr;
                ah[mi][0] = Au[r0 * 20 + kh + lc];
                ah[mi][1] = Au[(r0 + 8) * 20 + kh + lc];
                ah[mi][2] = Au[r0 * 20 + kh + 4 + lc];
                ah[mi][3] = Au[(r0 + 8) * 20 + kh + 4 + lc];
                al[mi][0] = Alu[r0 * 20 + kh + lc];
                al[mi][1] = Alu[(r0 + 8) * 20 + kh + lc];
                al[mi][2] = Alu[r0 * 20 + kh + 4 + lc];
                al[mi][3] = Alu[(r0 + 8) * 20 + kh + 4 + lc];
            }
            uint32_t bh[4][2], bl[4][2];
#pragma unroll
            for (int ni = 0; ni < 4; ++ni) {
                int nn = wn + ni * 8 + lr;
                bh[ni][0] = Bh[kh + lc][nn];
                bh[ni][1] = Bh[kh + 4 + lc][nn];
                bl[ni][0] = Bl[kh + lc][nn];
                bl[ni][1] = Bl[kh + 4 + lc][nn];
            }
#pragma unroll
            for (int mi = 0; mi < 4; ++mi)
#pragma unroll
                for (int ni = 0; ni < 4; ++ni) {
                    mma_bf16(acc[mi][ni], ah[mi], bh[ni][0], bh[ni][1]);
                    mma_bf16(acc[mi][ni], ah[mi], bl[ni][0], bl[ni][1]);
                    mma_bf16(acc[mi][ni], al[mi], bh[ni][0], bh[ni][1]);
                }
        }
        __syncthreads();
    }

#pragma unroll
    for (int mi = 0; mi < 4; ++mi)
#pragma unroll
        for (int ni = 0; ni < 4; ++ni) {
            int row = wm + mi * 16 + lr;
            int col = n0 + wn + ni * 8 + lc * 2;
            float* Cp = Cpart + ((size_t)z * 128 + row) * NPAD + col;
            *(float2*)Cp = make_float2(acc[mi][ni][0], acc[mi][ni][1]);
            *(float2*)(Cp + (size_t)8 * NPAD) = make_float2(acc[mi][ni][2], acc[mi][ni][3]);
        }
}

// ---------------- assemble h0 (counts computed inline) ----------------------
__global__ __launch_bounds__(256) void build_h0(const float* __restrict__ bqe,
                                                const float* __restrict__ bqn,
                                                const int* __restrict__ sg0,
                                                const int* __restrict__ sg1,
                                                const int* __restrict__ sg2) {
    __shared__ int scnt[3];
    int idx = blockIdx.x * 256 + threadIdx.x;   // 128*1024; 4 blocks per batch
    int b = idx >> 10, j = idx & 1023;

    if (threadIdx.x < 3) {
        const int* seg = (threadIdx.x == 0) ? sg0 : (threadIdx.x == 1) ? sg1 : sg2;
        int n = (threadIdx.x == 2) ? NEDGES : NNODES;
        int lo = 0, hi = n;
        while (lo < hi) { int m = (lo + hi) >> 1; if (seg[m] < b) lo = m + 1; else hi = m; }
        int s0 = lo; hi = n;
        while (lo < hi) { int m = (lo + hi) >> 1; if (seg[m] < b + 1) lo = m + 1; else hi = m; }
        int c = lo - s0;
        scnt[threadIdx.x] = (c < 1) ? 1 : c;
    }
    __syncthreads();

    float qs = 0.f;
#pragma unroll
    for (int z = 0; z < ZQ; ++z) qs += g_qpart[(size_t)z * (BQ * 1024) + idx];
    float r;
    if (j < 512) {
        float pe = 0.f;
#pragma unroll
        for (int s = 0; s < SEGS; ++s)
            pe += g_poolpart[(size_t)((2 * SEGS + s) * BQ + b) * HH + j];
        r = 2.f * (qs + bqe[j] + pe / (float)scnt[2]);
    } else {
        int jj = j - 512;
        float p0 = 0.f, p1 = 0.f;
#pragma unroll
        for (int s = 0; s < SEGS; ++s) {
            p0 += g_poolpart[(size_t)((0 * SEGS + s) * BQ + b) * HH + jj];
            p1 += g_poolpart[(size_t)((1 * SEGS + s) * BQ + b) * HH + jj];
        }
        r = 2.f * (qs + bqn[jj]) + p0 / (float)scnt[0] + p1 / (float)scnt[1];
    }
    g_h0[idx] = r;
}

// ---------------- reduce split-K + bias + elu -------------------------------
__global__ __launch_bounds__(256) void reduce_elu(const float* __restrict__ b1) {
    int idx = blockIdx.x * 256 + threadIdx.x;   // 128*2048
    float s = b1[idx & (MIDN - 1)];
#pragma unroll
    for (int z = 0; z < Z1; ++z) s += g_h1part[(size_t)z * (BQ * MIDN) + idx];
    g_h[idx] = (s > 0.f) ? s : expm1f(s);
}

// ---------------- reduce split-K (padded) + bias -> output ------------------
__global__ __launch_bounds__(256) void reduce_out(const float* __restrict__ b2,
                                                  float* __restrict__ out) {
    int idx = blockIdx.x * 256 + threadIdx.x;
    if (idx >= BQ * NANS) return;
    int b = idx / NANS, n = idx - b * NANS;
    float s = b2[n];
#pragma unroll
    for (int z = 0; z < Z2; ++z) s += g_outpart[((size_t)z * BQ + b) * W2PAD + n];
    out[idx] = s;
}

// ---------------- launcher ---------------------------------------------------
extern "C" void kernel_launch(void* const* d_in, const int* in_sizes, int n_in,
                              void* d_out, int out_size) {
    const float* question      = (const float*)d_in[0];
    const float* img_node_feat = (const float*)d_in[1];
    const float* kg_node_feat  = (const float*)d_in[2];
    const float* img_edge_feat = (const float*)d_in[3];
    const int*   img_node_seg  = (const int*)d_in[5];
    const int*   kg_node_seg   = (const int*)d_in[6];
    const int*   img_edge_seg  = (const int*)d_in[7];
    const float* Wqe = (const float*)d_in[9];
    const float* bqe = (const float*)d_in[10];
    const float* Wqn = (const float*)d_in[11];
    const float* bqn = (const float*)d_in[12];
    const float* W1  = (const float*)d_in[13];
    const float* b1  = (const float*)d_in[14];
    const float* W2  = (const float*)d_in[15];
    const float* b2  = (const float*)d_in[16];
    float* out = (float*)d_out;

    float *qpart, *h0, *h1part, *h, *outpart;
    cudaGetSymbolAddress((void**)&qpart,   g_qpart);
    cudaGetSymbolAddress((void**)&h0,      g_h0);
    cudaGetSymbolAddress((void**)&h1part,  g_h1part);
    cudaGetSymbolAddress((void**)&h,       g_h);
    cudaGetSymbolAddress((void**)&outpart, g_outpart);

    // 1) pools (3 planes, no conversion plane)
    seg_part<<<dim3(SEGS, BQ, 3), 128>>>(img_node_feat, kg_node_feat, img_edge_feat,
                                         img_node_seg, kg_node_seg, img_edge_seg);

    // 2) fused q projection, conversion fused into B loader: 8x16 = 128 CTAs
    gemm_mma_f<<<dim3(8, ZQ), 256>>>(question, 1024, Wqe, Wqn, 512, 512, 1024,
                                     qpart, 1024);

    // 3) assemble h0 (counts inline)
    build_h0<<<(BQ * 1024) / 256, 256>>>(bqe, bqn, img_node_seg, kg_node_seg,
                                         img_edge_seg);

    // 4) W1: 16x8 = 128 CTAs; + elu reduce
    gemm_mma_f<<<dim3(16, Z1), 256>>>(h0, 1024, W1, W1, 1 << 30, MIDN, MIDN,
                                      h1part, 1024);
    reduce_elu<<<(BQ * MIDN) / 256, 256>>>(b1);

    // 5) W2: 25x5 = 125 CTAs (odd N -> guarded scalar B loads); + reduce
    gemm_mma_f<<<dim3(25, Z2), 256>>>(h, MIDN, W2, W2, 1 << 30, NANS, W2PAD,
                                      outpart, 2048);
    reduce_out<<<(BQ * NANS + 255) / 256, 256>>>(b2, out);
}

// round 14
// speedup vs baseline: 2.4071x; 1.0709x over previous
#include <cuda_runtime.h>
#include <cuda_bf16.h>
#include <math.h>
#include <stdint.h>

#define HH      512
#define BQ      128
#define MIDN    2048
#define NANS    3129
#define W2PAD   3200
#define NNODES  131072
#define NEDGES  262144

#define SEGS    8
#define ZQ      16     // split-K for fused q projection
#define Z1      8      // split-K for W1
#define Z2      6      // split-K for W2 (150 CTAs)

// ---------------- scratch (static __device__, no allocation) ----------------
__device__ float g_poolpart[3 * SEGS * BQ * HH];
__device__ float g_qpart[ZQ * BQ * 1024];
__device__ float g_h0[BQ * 1024];
__device__ float g_h1part[Z1 * BQ * MIDN];
__device__ float g_h[BQ * MIDN];
__device__ float g_outpart[Z2 * BQ * W2PAD];

// ---------------- pool: fused segment-sum partials (3 planes) ---------------
__global__ __launch_bounds__(128) void seg_part(const float* __restrict__ f0,
                                                const float* __restrict__ f1,
                                                const float* __restrict__ f2,
                                                const int* __restrict__ sg0,
                                                const int* __restrict__ sg1,
                                                const int* __restrict__ sg2) {
    int arr = blockIdx.z;
    const float* feat = (arr == 0) ? f0 : (arr == 1) ? f1 : f2;
    const int*   seg  = (arr == 0) ? sg0 : (arr == 1) ? sg1 : sg2;
    int n = (arr == 2) ? NEDGES : NNODES;
    int b = blockIdx.y, s = blockIdx.x;

    int lo = 0, hi = n;
    while (lo < hi) { int m = (lo + hi) >> 1; if (seg[m] < b) lo = m + 1; else hi = m; }
    int st0 = lo; hi = n;
    while (lo < hi) { int m = (lo + hi) >> 1; if (seg[m] < b + 1) lo = m + 1; else hi = m; }
    int cnt = lo - st0;
    int r0 = st0 + (int)((long long)cnt * s / SEGS);
    int r1 = st0 + (int)((long long)cnt * (s + 1) / SEGS);

    const float4* p = (const float4*)feat + (size_t)r0 * 128 + threadIdx.x;
    float4 a0 = {0,0,0,0}, a1 = a0, a2 = a0, a3 = a0, a4 = a0, a5 = a0, a6 = a0, a7 = a0;
    int r = r0;
    for (; r + 8 <= r1; r += 8) {
        float4 v0 = __ldcs(p + 0*128), v1 = __ldcs(p + 1*128);
        float4 v2 = __ldcs(p + 2*128), v3 = __ldcs(p + 3*128);
        float4 v4 = __ldcs(p + 4*128), v5 = __ldcs(p + 5*128);
        float4 v6 = __ldcs(p + 6*128), v7 = __ldcs(p + 7*128);
        a0.x+=v0.x; a0.y+=v0.y; a0.z+=v0.z; a0.w+=v0.w;
        a1.x+=v1.x; a1.y+=v1.y; a1.z+=v1.z; a1.w+=v1.w;
        a2.x+=v2.x; a2.y+=v2.y; a2.z+=v2.z; a2.w+=v2.w;
        a3.x+=v3.x; a3.y+=v3.y; a3.z+=v3.z; a3.w+=v3.w;
        a4.x+=v4.x; a4.y+=v4.y; a4.z+=v4.z; a4.w+=v4.w;
        a5.x+=v5.x; a5.y+=v5.y; a5.z+=v5.z; a5.w+=v5.w;
        a6.x+=v6.x; a6.y+=v6.y; a6.z+=v6.z; a6.w+=v6.w;
        a7.x+=v7.x; a7.y+=v7.y; a7.z+=v7.z; a7.w+=v7.w;
        p += 8 * 128;
    }
    for (; r < r1; ++r) {
        float4 v = __ldcs(p);
        a0.x+=v.x; a0.y+=v.y; a0.z+=v.z; a0.w+=v.w;
        p += 128;
    }
    float4 t;
    t.x = ((a0.x+a1.x)+(a2.x+a3.x)) + ((a4.x+a5.x)+(a6.x+a7.x));
    t.y = ((a0.y+a1.y)+(a2.y+a3.y)) + ((a4.y+a5.y)+(a6.y+a7.y));
    t.z = ((a0.z+a1.z)+(a2.z+a3.z)) + ((a4.z+a5.z)+(a6.z+a7.z));
    t.w = ((a0.w+a1.w)+(a2.w+a3.w)) + ((a4.w+a5.w)+(a6.w+a7.w));
    float4* outp = (float4*)g_poolpart + (size_t)((arr * SEGS + s) * BQ + b) * 128 + threadIdx.x;
    *outp = t;
}

// ---------------- bf16 mma.sync GEMM, fused conversion, reg-prefetch --------
__device__ __forceinline__ void mma_bf16(float* c, const uint32_t* a,
                                         uint32_t b0, uint32_t b1) {
    asm volatile("mma.sync.aligned.m16n8k16.row.col.f32.bf16.bf16.f32 "
                 "{%0,%1,%2,%3}, {%4,%5,%6,%7}, {%8,%9}, {%0,%1,%2,%3};"
                 : "+f"(c[0]), "+f"(c[1]), "+f"(c[2]), "+f"(c[3])
                 : "r"(a[0]), "r"(a[1]), "r"(a[2]), "r"(a[3]), "r"(b0), "r"(b1));
}

__global__ __launch_bounds__(256) void gemm_mma_f(const float* __restrict__ A, int lda,
                                                  const float* __restrict__ B1,
                                                  const float* __restrict__ B2, int N1,
                                                  int Nreal, int NPAD,
                                                  float* __restrict__ Cpart, int K) {
    __shared__ __align__(16) __nv_bfloat16 Ah[128][40];
    __shared__ __align__(16) __nv_bfloat16 Al[128][40];
    __shared__ __align__(16) uint32_t Bh[16][136];
    __shared__ __align__(16) uint32_t Bl[16][136];

    const int tid = threadIdx.x, wid = tid >> 5, lane = tid & 31;
    const int wm = (wid >> 2) * 64, wn = (wid & 3) * 32;
    const int lr = lane >> 2, lc = lane & 3;

    const int z = blockIdx.y, Z = gridDim.y;
    const int chunks = K >> 5;
    const int c0 = chunks * z / Z, c1 = chunks * (z + 1) / Z;
    const int n0 = blockIdx.x * 128;

    const float* W; int nb;
    if (n0 < N1) { W = B1; nb = n0; } else { W = B2; nb = n0 - N1; }
    const bool full = (nb + 128 <= Nreal) && ((Nreal & 3) == 0);

    // loader lane coords (fixed per thread)
    const int la_r = tid >> 3, la_c = (tid & 7) << 2;            // A: 2 iters stride 32 rows? no: 4 iters q=tid+it*256
    const int lb_r = tid >> 5, lb_c = (tid & 31) << 2;           // B: 2 iters stride 8 rows

    float4 avr[4];
    float4 b0r[2], b1r[2];

    // ---- prefetch chunk c0 ----
    {
        const int k0 = c0 << 5;
#pragma unroll
        for (int it = 0; it < 4; ++it) {
            int r = la_r + it * 32;
            avr[it] = *(const float4*)(A + (size_t)r * lda + k0 + la_c);
        }
        const int k20 = k0 >> 1;
#pragma unroll
        for (int it = 0; it < 2; ++it) {
            int r = lb_r + it * 8;
            const float* p0 = W + (size_t)((k20 + r) * 2) * Nreal + nb + lb_c;
            const float* p1 = p0 + Nreal;
            if (full) {
                b0r[it] = *(const float4*)p0;
                b1r[it] = *(const float4*)p1;
            } else {
                float4 x0, x1;
                x0.x = (nb + lb_c + 0 < Nreal) ? p0[0] : 0.f;
                x0.y = (nb + lb_c + 1 < Nreal) ? p0[1] : 0.f;
                x0.z = (nb + lb_c + 2 < Nreal) ? p0[2] : 0.f;
                x0.w = (nb + lb_c + 3 < Nreal) ? p0[3] : 0.f;
                x1.x = (nb + lb_c + 0 < Nreal) ? p1[0] : 0.f;
                x1.y = (nb + lb_c + 1 < Nreal) ? p1[1] : 0.f;
                x1.z = (nb + lb_c + 2 < Nreal) ? p1[2] : 0.f;
                x1.w = (nb + lb_c + 3 < Nreal) ? p1[3] : 0.f;
                b0r[it] = x0; b1r[it] = x1;
            }
        }
    }

    float acc[4][4][4];
#pragma unroll
    for (int i = 0; i < 4; ++i)
#pragma unroll
        for (int j = 0; j < 4; ++j)
#pragma unroll
            for (int k = 0; k < 4; ++k) acc[i][j][k] = 0.f;

    const uint32_t* Au = (const uint32_t*)Ah;   // [128][20]
    const uint32_t* Alu = (const uint32_t*)Al;

    for (int c = c0; c < c1; ++c) {
        // ---- convert + store prefetched regs to smem ----
#pragma unroll
        for (int it = 0; it < 4; ++it) {
            float4 v = avr[it];
            int r = la_r + it * 32;
            __nv_bfloat16 h0 = __float2bfloat16_rn(v.x);
            __nv_bfloat16 h1 = __float2bfloat16_rn(v.y);
            __nv_bfloat16 h2 = __float2bfloat16_rn(v.z);
            __nv_bfloat16 h3 = __float2bfloat16_rn(v.w);
            __nv_bfloat162 hp0(h0, h1), hp1(h2, h3);
            __nv_bfloat162 lp0(__float2bfloat16_rn(v.x - __bfloat162float(h0)),
                               __float2bfloat16_rn(v.y - __bfloat162float(h1)));
            __nv_bfloat162 lp1(__float2bfloat16_rn(v.z - __bfloat162float(h2)),
                               __float2bfloat16_rn(v.w - __bfloat162float(h3)));
            *(uint2*)&Ah[r][la_c] = make_uint2(*(uint32_t*)&hp0, *(uint32_t*)&hp1);
            *(uint2*)&Al[r][la_c] = make_uint2(*(uint32_t*)&lp0, *(uint32_t*)&lp1);
        }
#pragma unroll
        for (int it = 0; it < 2; ++it) {
            int r = lb_r + it * 8;
            float v0[4] = {b0r[it].x, b0r[it].y, b0r[it].z, b0r[it].w};
            float v1[4] = {b1r[it].x, b1r[it].y, b1r[it].z, b1r[it].w};
            uint32_t hw[4], lw[4];
#pragma unroll
            for (int j = 0; j < 4; ++j) {
                __nv_bfloat16 h0 = __float2bfloat16_rn(v0[j]);
                __nv_bfloat16 h1 = __float2bfloat16_rn(v1[j]);
                __nv_bfloat162 hp(h0, h1);
                __nv_bfloat162 lp(__float2bfloat16_rn(v0[j] - __bfloat162float(h0)),
                                  __float2bfloat16_rn(v1[j] - __bfloat162float(h1)));
                hw[j] = *(uint32_t*)&hp;
                lw[j] = *(uint32_t*)&lp;
            }
            *(uint4*)&Bh[r][lb_c] = make_uint4(hw[0], hw[1], hw[2], hw[3]);
            *(uint4*)&Bl[r][lb_c] = make_uint4(lw[0], lw[1], lw[2], lw[3]);
        }
        __syncthreads();

        // ---- issue next chunk's global loads (overlap with compute) ----
        if (c + 1 < c1) {
            const int k0n = (c + 1) << 5;
#pragma unroll
            for (int it = 0; it < 4; ++it) {
                int r = la_r + it * 32;
                avr[it] = *(const float4*)(A + (size_t)r * lda + k0n + la_c);
            }
            const int k20n = k0n >> 1;
#pragma unroll
            for (int it = 0; it < 2; ++it) {
                int r = lb_r + it * 8;
                const float* p0 = W + (size_t)((k20n + r) * 2) * Nreal + nb + lb_c;
                const float* p1 = p0 + Nreal;
                if (full) {
                    b0r[it] = *(const float4*)p0;
                    b1r[it] = *(const float4*)p1;
                } else {
                    float4 x0, x1;
                    x0.x = (nb + lb_c + 0 < Nreal) ? p0[0] : 0.f;
                    x0.y = (nb + lb_c + 1 < Nreal) ? p0[1] : 0.f;
                    x0.z = (nb + lb_c + 2 < Nreal) ? p0[2] : 0.f;
                    x0.w = (nb + lb_c + 3 < Nreal) ? p0[3] : 0.f;
                    x1.x = (nb + lb_c + 0 < Nreal) ? p1[0] : 0.f;
                    x1.y = (nb + lb_c + 1 < Nreal) ? p1[1] : 0.f;
                    x1.z = (nb + lb_c + 2 < Nreal) ? p1[2] : 0.f;
                    x1.w = (nb + lb_c + 3 < Nreal) ? p1[3] : 0.f;
                    b0r[it] = x0; b1r[it] = x1;
                }
            }
        }

        // ---- compute from smem ----
#pragma unroll
        for (int ks = 0; ks < 2; ++ks) {
            const int kh = ks * 8;
            uint32_t ah[4][4], al[4][4];
#pragma unroll
            for (int mi = 0; mi < 4; ++mi) {
                int r0 = wm + mi * 16 + lr;
                ah[mi][0] = Au[r0 * 20 + kh + lc];
                ah[mi][1] = Au[(r0 + 8) * 20 + kh + lc];
                ah[mi][2] = Au[r0 * 20 + kh + 4 + lc];
                ah[mi][3] = Au[(r0 + 8) * 20 + kh + 4 + lc];
                al[mi][0] = Alu[r0 * 20 + kh + lc];
                al[mi][1] = Alu[(r0 + 8) * 20 + kh + lc];
                al[mi][2] = Alu[r0 * 20 + kh + 4 + lc];
                al[mi][3] = Alu[(r0 + 8) * 20 + kh + 4 + lc];
            }
            uint32_t bh[4][2], bl[4][2];
#pragma unroll
            for (int ni = 0; ni < 4; ++ni) {
                int nn = wn + ni * 8 + lr;
                bh[ni][0] = Bh[kh + lc][nn];
                bh[ni][1] = Bh[kh + 4 + lc][nn];
                bl[ni][0] = Bl[kh + lc][nn];
                bl[ni][1] = Bl[kh + 4 + lc][nn];
            }
#pragma unroll
            for (int mi = 0; mi < 4; ++mi)
#pragma unroll
                for (int ni = 0; ni < 4; ++ni) {
                    mma_bf16(acc[mi][ni], ah[mi], bh[ni][0], bh[ni][1]);
                    mma_bf16(acc[mi][ni], ah[mi], bl[ni][0], bl[ni][1]);
                    mma_bf16(acc[mi][ni], al[mi], bh[ni][0], bh[ni][1]);
                }
        }
        __syncthreads();
    }

#pragma unroll
    for (int mi = 0; mi < 4; ++mi)
#pragma unroll
        for (int ni = 0; ni < 4; ++ni) {
            int row = wm + mi * 16 + lr;
            int col = n0 + wn + ni * 8 + lc * 2;
            float* Cp = Cpart + ((size_t)z * 128 + row) * NPAD + col;
            *(float2*)Cp = make_float2(acc[mi][ni][0], acc[mi][ni][1]);
            *(float2*)(Cp + (size_t)8 * NPAD) = make_float2(acc[mi][ni][2], acc[mi][ni][3]);
        }
}

// ---------------- assemble h0 (counts computed inline) ----------------------
__global__ __launch_bounds__(256) void build_h0(const float* __restrict__ bqe,
                                                const float* __restrict__ bqn,
                                                const int* __restrict__ sg0,
                                                const int* __restrict__ sg1,
                                                const int* __restrict__ sg2) {
    __shared__ int scnt[3];
    int idx = blockIdx.x * 256 + threadIdx.x;   // 128*1024; 4 blocks per batch
    int b = idx >> 10, j = idx & 1023;

    if (threadIdx.x < 3) {
        const int* seg = (threadIdx.x == 0) ? sg0 : (threadIdx.x == 1) ? sg1 : sg2;
        int n = (threadIdx.x == 2) ? NEDGES : NNODES;
        int lo = 0, hi = n;
        while (lo < hi) { int m = (lo + hi) >> 1; if (seg[m] < b) lo = m + 1; else hi = m; }
        int s0 = lo; hi = n;
        while (lo < hi) { int m = (lo + hi) >> 1; if (seg[m] < b + 1) lo = m + 1; else hi = m; }
        int c = lo - s0;
        scnt[threadIdx.x] = (c < 1) ? 1 : c;
    }
    __syncthreads();

    float qs = 0.f;
#pragma unroll
    for (int z = 0; z < ZQ; ++z) qs += g_qpart[(size_t)z * (BQ * 1024) + idx];
    float r;
    if (j < 512) {
        float pe = 0.f;
#pragma unroll
        for (int s = 0; s < SEGS; ++s)
            pe += g_poolpart[(size_t)((2 * SEGS + s) * BQ + b) * HH + j];
        r = 2.f * (qs + bqe[j] + pe / (float)scnt[2]);
    } else {
        int jj = j - 512;
        float p0 = 0.f, p1 = 0.f;
#pragma unroll
        for (int s = 0; s < SEGS; ++s) {
            p0 += g_poolpart[(size_t)((0 * SEGS + s) * BQ + b) * HH + jj];
            p1 += g_poolpart[(size_t)((1 * SEGS + s) * BQ + b) * HH + jj];
        }
        r = 2.f * (qs + bqn[jj]) + p0 / (float)scnt[0] + p1 / (float)scnt[1];
    }
    g_h0[idx] = r;
}

// ---------------- reduce split-K + bias + elu -------------------------------
__global__ __launch_bounds__(256) void reduce_elu(const float* __restrict__ b1) {
    int idx = blockIdx.x * 256 + threadIdx.x;   // 128*2048
    float s = b1[idx & (MIDN - 1)];
#pragma unroll
    for (int z = 0; z < Z1; ++z) s += g_h1part[(size_t)z * (BQ * MIDN) + idx];
    g_h[idx] = (s > 0.f) ? s : expm1f(s);
}

// ---------------- reduce split-K (padded) + bias -> output ------------------
__global__ __launch_bounds__(256) void reduce_out(const float* __restrict__ b2,
                                                  float* __restrict__ out) {
    int idx = blockIdx.x * 256 + threadIdx.x;
    if (idx >= BQ * NANS) return;
    int b = idx / NANS, n = idx - b * NANS;
    float s = b2[n];
#pragma unroll
    for (int z = 0; z < Z2; ++z) s += g_outpart[((size_t)z * BQ + b) * W2PAD + n];
    out[idx] = s;
}

// ---------------- launcher ---------------------------------------------------
extern "C" void kernel_launch(void* const* d_in, const int* in_sizes, int n_in,
                              void* d_out, int out_size) {
    const float* question      = (const float*)d_in[0];
    const float* img_node_feat = (const float*)d_in[1];
    const float* kg_node_feat  = (const float*)d_in[2];
    const float* img_edge_feat = (const float*)d_in[3];
    const int*   img_node_seg  = (const int*)d_in[5];
    const int*   kg_node_seg   = (const int*)d_in[6];
    const int*   img_edge_seg  = (const int*)d_in[7];
    const float* Wqe = (const float*)d_in[9];
    const float* bqe = (const float*)d_in[10];
    const float* Wqn = (const float*)d_in[11];
    const float* bqn = (const float*)d_in[12];
    const float* W1  = (const float*)d_in[13];
    const float* b1  = (const float*)d_in[14];
    const float* W2  = (const float*)d_in[15];
    const float* b2  = (const float*)d_in[16];
    float* out = (float*)d_out;

    float *qpart, *h0, *h1part, *h, *outpart;
    cudaGetSymbolAddress((void**)&qpart,   g_qpart);
    cudaGetSymbolAddress((void**)&h0,      g_h0);
    cudaGetSymbolAddress((void**)&h1part,  g_h1part);
    cudaGetSymbolAddress((void**)&h,       g_h);
    cudaGetSymbolAddress((void**)&outpart, g_outpart);

    // 1) pools (3 planes)
    seg_part<<<dim3(SEGS, BQ, 3), 128>>>(img_node_feat, kg_node_feat, img_edge_feat,
                                         img_node_seg, kg_node_seg, img_edge_seg);

    // 2) fused q projection (pipelined): 8x16 = 128 CTAs
    gemm_mma_f<<<dim3(8, ZQ), 256>>>(question, 1024, Wqe, Wqn, 512, 512, 1024,
                                     qpart, 1024);

    // 3) assemble h0 (counts inline)
    build_h0<<<(BQ * 1024) / 256, 256>>>(bqe, bqn, img_node_seg, kg_node_seg,
                                         img_edge_seg);

    // 4) W1 (pipelined): 16x8 = 128 CTAs; + elu reduce
    gemm_mma_f<<<dim3(16, Z1), 256>>>(h0, 1024, W1, W1, 1 << 30, MIDN, MIDN,
                                      h1part, 1024);
    reduce_elu<<<(BQ * MIDN) / 256, 256>>>(b1);

    // 5) W2 (pipelined): 25x6 = 150 CTAs (odd N -> guarded B loads); + reduce
    gemm_mma_f<<<dim3(25, Z2), 256>>>(h, MIDN, W2, W2, 1 << 30, NANS, W2PAD,
                                      outpart, 2048);
    reduce_out<<<(BQ * NANS + 255) / 256, 256>>>(b2, out);
}

// round 15
// speedup vs baseline: 2.5746x; 1.0696x over previous
#include <cuda_runtime.h>
#include <cuda_bf16.h>
#include <math.h>
#include <stdint.h>

#define HH      512
#define BQ      128
#define MIDN    2048
#define NANS    3129
#define W2PAD   3200
#define NNODES  131072
#define NEDGES  262144

#define SEGS    8
#define ZQ      16     // split-K for fused q projection
#define Z1      8      // split-K for W1
#define Z2      6      // split-K for W2 (150 CTAs)

// ---------------- scratch (static __device__, no allocation) ----------------
__device__ int   g_segoff[3 * 129];          // boundary table: [arr][b] start row
__device__ float g_poolpart[3 * SEGS * BQ * HH];
__device__ float g_qpart[ZQ * BQ * 1024];
__device__ float g_h0[BQ * 1024];
__device__ float g_h1part[Z1 * BQ * MIDN];
__device__ float g_h[BQ * MIDN];
__device__ float g_outpart[Z2 * BQ * W2PAD];

// ---------------- boundary table: one coalesced scan, no searches -----------
// off[arr][b] = lower_bound(seg, b); off[arr][128] = n. Each entry written by
// exactly one thread (the one owning the transition), so no atomics needed.
__global__ __launch_bounds__(256) void seg_bounds(const int* __restrict__ sg0,
                                                  const int* __restrict__ sg1,
                                                  const int* __restrict__ sg2) {
    int gid = blockIdx.x * 256 + threadIdx.x;
    const int stride = gridDim.x * 256;
    const int tot = NNODES + NNODES + NEDGES;
    for (int t = gid; t < tot; t += stride) {
        int arr, i, n;
        if (t < NNODES)            { arr = 0; i = t;              n = NNODES; }
        else if (t < 2 * NNODES)   { arr = 1; i = t - NNODES;     n = NNODES; }
        else                       { arr = 2; i = t - 2 * NNODES; n = NEDGES; }
        const int* seg = (arr == 0) ? sg0 : (arr == 1) ? sg1 : sg2;
        int* off = g_segoff + arr * 129;
        int v = seg[i];
        if (i == 0) {
            for (int b = 0; b <= v; ++b) off[b] = 0;
        } else {
            int pv = seg[i - 1];
            for (int b = pv + 1; b <= v; ++b) off[b] = i;
        }
        if (i == n - 1) {
            for (int b = v + 1; b <= 128; ++b) off[b] = n;
        }
    }
}

// ---------------- pool: fused segment-sum partials (3 planes) ---------------
__global__ __launch_bounds__(128) void seg_part(const float* __restrict__ f0,
                                                const float* __restrict__ f1,
                                                const float* __restrict__ f2) {
    int arr = blockIdx.z;
    const float* feat = (arr == 0) ? f0 : (arr == 1) ? f1 : f2;
    int b = blockIdx.y, s = blockIdx.x;

    int st0 = g_segoff[arr * 129 + b];
    int cnt = g_segoff[arr * 129 + b + 1] - st0;
    int r0 = st0 + (int)((long long)cnt * s / SEGS);
    int r1 = st0 + (int)((long long)cnt * (s + 1) / SEGS);

    const float4* p = (const float4*)feat + (size_t)r0 * 128 + threadIdx.x;
    float4 a0 = {0,0,0,0}, a1 = a0, a2 = a0, a3 = a0, a4 = a0, a5 = a0, a6 = a0, a7 = a0;
    int r = r0;
    for (; r + 8 <= r1; r += 8) {
        float4 v0 = __ldcs(p + 0*128), v1 = __ldcs(p + 1*128);
        float4 v2 = __ldcs(p + 2*128), v3 = __ldcs(p + 3*128);
        float4 v4 = __ldcs(p + 4*128), v5 = __ldcs(p + 5*128);
        float4 v6 = __ldcs(p + 6*128), v7 = __ldcs(p + 7*128);
        a0.x+=v0.x; a0.y+=v0.y; a0.z+=v0.z; a0.w+=v0.w;
        a1.x+=v1.x; a1.y+=v1.y; a1.z+=v1.z; a1.w+=v1.w;
        a2.x+=v2.x; a2.y+=v2.y; a2.z+=v2.z; a2.w+=v2.w;
        a3.x+=v3.x; a3.y+=v3.y; a3.z+=v3.z; a3.w+=v3.w;
        a4.x+=v4.x; a4.y+=v4.y; a4.z+=v4.z; a4.w+=v4.w;
        a5.x+=v5.x; a5.y+=v5.y; a5.z+=v5.z; a5.w+=v5.w;
        a6.x+=v6.x; a6.y+=v6.y; a6.z+=v6.z; a6.w+=v6.w;
        a7.x+=v7.x; a7.y+=v7.y; a7.z+=v7.z; a7.w+=v7.w;
        p += 8 * 128;
    }
    for (; r < r1; ++r) {
        float4 v = __ldcs(p);
        a0.x+=v.x; a0.y+=v.y; a0.z+=v.z; a0.w+=v.w;
        p += 128;
    }
    float4 t;
    t.x = ((a0.x+a1.x)+(a2.x+a3.x)) + ((a4.x+a5.x)+(a6.x+a7.x));
    t.y = ((a0.y+a1.y)+(a2.y+a3.y)) + ((a4.y+a5.y)+(a6.y+a7.y));
    t.z = ((a0.z+a1.z)+(a2.z+a3.z)) + ((a4.z+a5.z)+(a6.z+a7.z));
    t.w = ((a0.w+a1.w)+(a2.w+a3.w)) + ((a4.w+a5.w)+(a6.w+a7.w));
    float4* outp = (float4*)g_poolpart + (size_t)((arr * SEGS + s) * BQ + b) * 128 + threadIdx.x;
    *outp = t;
}

// ---------------- bf16 mma.sync GEMM, fused conversion, reg-prefetch --------
__device__ __forceinline__ void mma_bf16(float* c, const uint32_t* a,
                                         uint32_t b0, uint32_t b1) {
    asm volatile("mma.sync.aligned.m16n8k16.row.col.f32.bf16.bf16.f32 "
                 "{%0,%1,%2,%3}, {%4,%5,%6,%7}, {%8,%9}, {%0,%1,%2,%3};"
                 : "+f"(c[0]), "+f"(c[1]), "+f"(c[2]), "+f"(c[3])
                 : "r"(a[0]), "r"(a[1]), "r"(a[2]), "r"(a[3]), "r"(b0), "r"(b1));
}

__global__ __launch_bounds__(256) void gemm_mma_f(const float* __restrict__ A, int lda,
                                                  const float* __restrict__ B1,
                                                  const float* __restrict__ B2, int N1,
                                                  int Nreal, int NPAD,
                                                  float* __restrict__ Cpart, int K) {
    __shared__ __align__(16) __nv_bfloat16 Ah[128][40];
    __shared__ __align__(16) __nv_bfloat16 Al[128][40];
    __shared__ __align__(16) uint32_t Bh[16][136];
    __shared__ __align__(16) uint32_t Bl[16][136];

    const int tid = threadIdx.x, wid = tid >> 5, lane = tid & 31;
    const int wm = (wid >> 2) * 64, wn = (wid & 3) * 32;
    const int lr = lane >> 2, lc = lane & 3;

    const int z = blockIdx.y, Z = gridDim.y;
    const int chunks = K >> 5;
    const int c0 = chunks * z / Z, c1 = chunks * (z + 1) / Z;
    const int n0 = blockIdx.x * 128;

    const float* W; int nb;
    if (n0 < N1) { W = B1; nb = n0; } else { W = B2; nb = n0 - N1; }
    const bool full = (nb + 128 <= Nreal) && ((Nreal & 3) == 0);

    const int la_r = tid >> 3, la_c = (tid & 7) << 2;
    const int lb_r = tid >> 5, lb_c = (tid & 31) << 2;

    float4 avr[4];
    float4 b0r[2], b1r[2];

    // ---- prefetch chunk c0 ----
    {
        const int k0 = c0 << 5;
#pragma unroll
        for (int it = 0; it < 4; ++it) {
            int r = la_r + it * 32;
            avr[it] = *(const float4*)(A + (size_t)r * lda + k0 + la_c);
        }
        const int k20 = k0 >> 1;
#pragma unroll
        for (int it = 0; it < 2; ++it) {
            int r = lb_r + it * 8;
            const float* p0 = W + (size_t)((k20 + r) * 2) * Nreal + nb + lb_c;
            const float* p1 = p0 + Nreal;
            if (full) {
                b0r[it] = *(const float4*)p0;
                b1r[it] = *(const float4*)p1;
            } else {
                float4 x0, x1;
                x0.x = (nb + lb_c + 0 < Nreal) ? p0[0] : 0.f;
                x0.y = (nb + lb_c + 1 < Nreal) ? p0[1] : 0.f;
                x0.z = (nb + lb_c + 2 < Nreal) ? p0[2] : 0.f;
                x0.w = (nb + lb_c + 3 < Nreal) ? p0[3] : 0.f;
                x1.x = (nb + lb_c + 0 < Nreal) ? p1[0] : 0.f;
                x1.y = (nb + lb_c + 1 < Nreal) ? p1[1] : 0.f;
                x1.z = (nb + lb_c + 2 < Nreal) ? p1[2] : 0.f;
                x1.w = (nb + lb_c + 3 < Nreal) ? p1[3] : 0.f;
                b0r[it] = x0; b1r[it] = x1;
            }
        }
    }

    float acc[4][4][4];
#pragma unroll
    for (int i = 0; i < 4; ++i)
#pragma unroll
        for (int j = 0; j < 4; ++j)
#pragma unroll
            for (int k = 0; k < 4; ++k) acc[i][j][k] = 0.f;

    const uint32_t* Au = (const uint32_t*)Ah;   // [128][20]
    const uint32_t* Alu = (const uint32_t*)Al;

    for (int c = c0; c < c1; ++c) {
#pragma unroll
        for (int it = 0; it < 4; ++it) {
            float4 v = avr[it];
            int r = la_r + it * 32;
            __nv_bfloat16 h0 = __float2bfloat16_rn(v.x);
            __nv_bfloat16 h1 = __float2bfloat16_rn(v.y);
            __nv_bfloat16 h2 = __float2bfloat16_rn(v.z);
            __nv_bfloat16 h3 = __float2bfloat16_rn(v.w);
            __nv_bfloat162 hp0(h0, h1), hp1(h2, h3);
            __nv_bfloat162 lp0(__float2bfloat16_rn(v.x - __bfloat162float(h0)),
                               __float2bfloat16_rn(v.y - __bfloat162float(h1)));
            __nv_bfloat162 lp1(__float2bfloat16_rn(v.z - __bfloat162float(h2)),
                               __float2bfloat16_rn(v.w - __bfloat162float(h3)));
            *(uint2*)&Ah[r][la_c] = make_uint2(*(uint32_t*)&hp0, *(uint32_t*)&hp1);
            *(uint2*)&Al[r][la_c] = make_uint2(*(uint32_t*)&lp0, *(uint32_t*)&lp1);
        }
#pragma unroll
        for (int it = 0; it < 2; ++it) {
            int r = lb_r + it * 8;
            float v0[4] = {b0r[it].x, b0r[it].y, b0r[it].z, b0r[it].w};
            float v1[4] = {b1r[it].x, b1r[it].y, b1r[it].z, b1r[it].w};
            uint32_t hw[4], lw[4];
#pragma unroll
            for (int j = 0; j < 4; ++j) {
                __nv_bfloat16 h0 = __float2bfloat16_rn(v0[j]);
                __nv_bfloat16 h1 = __float2bfloat16_rn(v1[j]);
                __nv_bfloat162 hp(h0, h1);
                __nv_bfloat162 lp(__float2bfloat16_rn(v0[j] - __bfloat162float(h0)),
                                  __float2bfloat16_rn(v1[j] - __bfloat162float(h1)));
                hw[j] = *(uint32_t*)&hp;
                lw[j] = *(uint32_t*)&lp;
            }
            *(uint4*)&Bh[r][lb_c] = make_uint4(hw[0], hw[1], hw[2], hw[3]);
            *(uint4*)&Bl[r][lb_c] = make_uint4(lw[0], lw[1], lw[2], lw[3]);
        }
        __syncthreads();

        if (c + 1 < c1) {
            const int k0n = (c + 1) << 5;
#pragma unroll
            for (int it = 0; it < 4; ++it) {
                int r = la_r + it * 32;
                avr[it] = *(const float4*)(A + (size_t)r * lda + k0n + la_c);
            }
            const int k20n = k0n >> 1;
#pragma unroll
            for (int it = 0; it < 2; ++it) {
                int r = lb_r + it * 8;
                const float* p0 = W + (size_t)((k20n + r) * 2) * Nreal + nb + lb_c;
                const float* p1 = p0 + Nreal;
                if (full) {
                    b0r[it] = *(const float4*)p0;
                    b1r[it] = *(const float4*)p1;
                } else {
                    float4 x0, x1;
                    x0.x = (nb + lb_c + 0 < Nreal) ? p0[0] : 0.f;
                    x0.y = (nb + lb_c + 1 < Nreal) ? p0[1] : 0.f;
                    x0.z = (nb + lb_c + 2 < Nreal) ? p0[2] : 0.f;
                    x0.w = (nb + lb_c + 3 < Nreal) ? p0[3] : 0.f;
                    x1.x = (nb + lb_c + 0 < Nreal) ? p1[0] : 0.f;
                    x1.y = (nb + lb_c + 1 < Nreal) ? p1[1] : 0.f;
                    x1.z = (nb + lb_c + 2 < Nreal) ? p1[2] : 0.f;
                    x1.w = (nb + lb_c + 3 < Nreal) ? p1[3] : 0.f;
                    b0r[it] = x0; b1r[it] = x1;
                }
            }
        }

#pragma unroll
        for (int ks = 0; ks < 2; ++ks) {
            const int kh = ks * 8;
            uint32_t ah[4][4], al[4][4];
#pragma unroll
            for (int mi = 0; mi < 4; ++mi) {
                int r0 = wm + mi * 16 + lr;
                ah[mi][0] = Au[r0 * 20 + kh + lc];
                ah[mi][1] = Au[(r0 + 8) * 20 + kh + lc];
                ah[mi][2] = Au[r0 * 20 + kh + 4 + lc];
                ah[mi][3] = Au[(r0 + 8) * 20 + kh + 4 + lc];
                al[mi][0] = Alu[r0 * 20 + kh + lc];
                al[mi][1] = Alu[(r0 + 8) * 20 + kh + lc];
                al[mi][2] = Alu[r0 * 20 + kh + 4 + lc];
                al[mi][3] = Alu[(r0 + 8) * 20 + kh + 4 + lc];
            }
            uint32_t bh[4][2], bl[4][2];
#pragma unroll
            for (int ni = 0; ni < 4; ++ni) {
                int nn = wn + ni * 8 + lr;
                bh[ni][0] = Bh[kh + lc][nn];
                bh[ni][1] = Bh[kh + 4 + lc][nn];
                bl[ni][0] = Bl[kh + lc][nn];
                bl[ni][1] = Bl[kh + 4 + lc][nn];
            }
#pragma unroll
            for (int mi = 0; mi < 4; ++mi)
#pragma unroll
                for (int ni = 0; ni < 4; ++ni) {
                    mma_bf16(acc[mi][ni], ah[mi], bh[ni][0], bh[ni][1]);
                    mma_bf16(acc[mi][ni], ah[mi], bl[ni][0], bl[ni][1]);
                    mma_bf16(acc[mi][ni], al[mi], bh[ni][0], bh[ni][1]);
                }
        }
        __syncthreads();
    }

#pragma unroll
    for (int mi = 0; mi < 4; ++mi)
#pragma unroll
        for (int ni = 0; ni < 4; ++ni) {
            int row = wm + mi * 16 + lr;
            int col = n0 + wn + ni * 8 + lc * 2;
            float* Cp = Cpart + ((size_t)z * 128 + row) * NPAD + col;
            *(float2*)Cp = make_float2(acc[mi][ni][0], acc[mi][ni][1]);
            *(float2*)(Cp + (size_t)8 * NPAD) = make_float2(acc[mi][ni][2], acc[mi][ni][3]);
        }
}

// ---------------- assemble h0 (counts from boundary table) ------------------
__global__ __launch_bounds__(256) void build_h0(const float* __restrict__ bqe,
                                                const float* __restrict__ bqn) {
    __shared__ int scnt[3];
    int idx = blockIdx.x * 256 + threadIdx.x;   // 128*1024; 4 blocks per batch
    int b = idx >> 10, j = idx & 1023;

    if (threadIdx.x < 3) {
        int c = g_segoff[threadIdx.x * 129 + b + 1] - g_segoff[threadIdx.x * 129 + b];
        scnt[threadIdx.x] = (c < 1) ? 1 : c;
    }
    __syncthreads();

    float qs = 0.f;
#pragma unroll
    for (int z = 0; z < ZQ; ++z) qs += g_qpart[(size_t)z * (BQ * 1024) + idx];
    float r;
    if (j < 512) {
        float pe = 0.f;
#pragma unroll
        for (int s = 0; s < SEGS; ++s)
            pe += g_poolpart[(size_t)((2 * SEGS + s) * BQ + b) * HH + j];
        r = 2.f * (qs + bqe[j] + pe / (float)scnt[2]);
    } else {
        int jj = j - 512;
        float p0 = 0.f, p1 = 0.f;
#pragma unroll
        for (int s = 0; s < SEGS; ++s) {
            p0 += g_poolpart[(size_t)((0 * SEGS + s) * BQ + b) * HH + jj];
            p1 += g_poolpart[(size_t)((1 * SEGS + s) * BQ + b) * HH + jj];
        }
        r = 2.f * (qs + bqn[jj]) + p0 / (float)scnt[0] + p1 / (float)scnt[1];
    }
    g_h0[idx] = r;
}

// ---------------- reduce split-K + bias + elu -------------------------------
__global__ __launch_bounds__(256) void reduce_elu(const float* __restrict__ b1) {
    int idx = blockIdx.x * 256 + threadIdx.x;   // 128*2048
    float s = b1[idx & (MIDN - 1)];
#pragma unroll
    for (int z = 0; z < Z1; ++z) s += g_h1part[(size_t)z * (BQ * MIDN) + idx];
    g_h[idx] = (s > 0.f) ? s : expm1f(s);
}

// ---------------- reduce split-K (padded) + bias -> output ------------------
__global__ __launch_bounds__(256) void reduce_out(const float* __restrict__ b2,
                                                  float* __restrict__ out) {
    int idx = blockIdx.x * 256 + threadIdx.x;
    if (idx >= BQ * NANS) return;
    int b = idx / NANS, n = idx - b * NANS;
    float s = b2[n];
#pragma unroll
    for (int z = 0; z < Z2; ++z) s += g_outpart[((size_t)z * BQ + b) * W2PAD + n];
    out[idx] = s;
}

// ---------------- launcher ---------------------------------------------------
extern "C" void kernel_launch(void* const* d_in, const int* in_sizes, int n_in,
                              void* d_out, int out_size) {
    const float* question      = (const float*)d_in[0];
    const float* img_node_feat = (const float*)d_in[1];
    const float* kg_node_feat  = (const float*)d_in[2];
    const float* img_edge_feat = (const float*)d_in[3];
    const int*   img_node_seg  = (const int*)d_in[5];
    const int*   kg_node_seg   = (const int*)d_in[6];
    const int*   img_edge_seg  = (const int*)d_in[7];
    const float* Wqe = (const float*)d_in[9];
    const float* bqe = (const float*)d_in[10];
    const float* Wqn = (const float*)d_in[11];
    const float* bqn = (const float*)d_in[12];
    const float* W1  = (const float*)d_in[13];
    const float* b1  = (const float*)d_in[14];
    const float* W2  = (const float*)d_in[15];
    const float* b2  = (const float*)d_in[16];
    float* out = (float*)d_out;

    float *qpart, *h0, *h1part, *h, *outpart;
    cudaGetSymbolAddress((void**)&qpart,   g_qpart);
    cudaGetSymbolAddress((void**)&h0,      g_h0);
    cudaGetSymbolAddress((void**)&h1part,  g_h1part);
    cudaGetSymbolAddress((void**)&h,       g_h);
    cudaGetSymbolAddress((void**)&outpart, g_outpart);

    // 0) boundary table (one coalesced scan; replaces all binary searches)
    seg_bounds<<<2048, 256>>>(img_node_seg, kg_node_seg, img_edge_seg);

    // 1) pools (3 planes, boundaries from table)
    seg_part<<<dim3(SEGS, BQ, 3), 128>>>(img_node_feat, kg_node_feat, img_edge_feat);

    // 2) fused q projection (pipelined): 8x16 = 128 CTAs
    gemm_mma_f<<<dim3(8, ZQ), 256>>>(question, 1024, Wqe, Wqn, 512, 512, 1024,
                                     qpart, 1024);

    // 3) assemble h0 (counts from table)
    build_h0<<<(BQ * 1024) / 256, 256>>>(bqe, bqn);

    // 4) W1 (pipelined): 16x8 = 128 CTAs; + elu reduce
    gemm_mma_f<<<dim3(16, Z1), 256>>>(h0, 1024, W1, W1, 1 << 30, MIDN, MIDN,
                                      h1part, 1024);
    reduce_elu<<<(BQ * MIDN) / 256, 256>>>(b1);

    // 5) W2 (pipelined): 25x6 = 150 CTAs (odd N -> guarded B loads); + reduce
    gemm_mma_f<<<dim3(25, Z2), 256>>>(h, MIDN, W2, W2, 1 << 30, NANS, W2PAD,
                                      outpart, 2048);
    reduce_out<<<(BQ * NANS + 255) / 256, 256>>>(b2, out);
}